// round 1
// baseline (speedup 1.0000x reference)
#include <cuda_runtime.h>

#define IW   512            // image width/height
#define NB   4              // batch
#define NT   180            // angles
#define PAD  128
#define PW   (IW + 2*PAD)   // 768 padded dim
#define NCH  4              // h-chunks
#define HCH  (IW / NCH)     // 128 h per chunk
#define IMG_STRIDE (IW*IW)  // 262144 floats per image

// Scratch (static device memory: allowed; no allocations)
__device__ float4 g_img [PW * PW];   // padded, batch-packed image        (9.4 MB)
__device__ float4 g_imgT[PW * PW];   // padded, batch-packed transposed   (9.4 MB)
__device__ float4 g_partial[NCH * NT * IW];  // per-chunk partial sums    (5.9 MB)

// ---------------------------------------------------------------------------
// Prep: build zero-padded batch-packed image and its transpose.
// ---------------------------------------------------------------------------
__global__ void prep_kernel(const float* __restrict__ x) {
    int idx = blockIdx.x * blockDim.x + threadIdx.x;
    if (idx >= PW * PW) return;
    int row = idx / PW;
    int col = idx - row * PW;
    int r = row - PAD;
    int c = col - PAD;
    float4 v  = make_float4(0.f, 0.f, 0.f, 0.f);
    float4 vt = v;
    if ((unsigned)r < (unsigned)IW && (unsigned)c < (unsigned)IW) {
        int o  = r * IW + c;     // normal
        v.x  = x[o];
        v.y  = x[o +     IMG_STRIDE];
        v.z  = x[o + 2 * IMG_STRIDE];
        v.w  = x[o + 3 * IMG_STRIDE];
        int ot = c * IW + r;     // transposed
        vt.x = x[ot];
        vt.y = x[ot +     IMG_STRIDE];
        vt.z = x[ot + 2 * IMG_STRIDE];
        vt.w = x[ot + 3 * IMG_STRIDE];
    }
    g_img [idx] = v;
    g_imgT[idx] = vt;
}

// ---------------------------------------------------------------------------
// Radon: block = (theta, w-tile of 64, h-chunk of 128). 256 threads.
// Warp footprint: 8 w-lanes x 4 h-sublanes (dense rotated patch).
// Each thread: 32 samples (h stepping by 4), accumulating 4 batch sums.
// ---------------------------------------------------------------------------
__global__ __launch_bounds__(256) void radon_kernel(const float* __restrict__ theta) {
    const int t    = blockIdx.x;
    const int wtl  = blockIdx.y * 64;
    const int ch   = blockIdx.z;
    const int tid  = threadIdx.x;
    const int warp = tid >> 5;
    const int lane = tid & 31;
    const int wl   = lane & 7;   // w sub-lane
    const int hl   = lane >> 3;  // h sub-lane (0..3)
    const int w    = wtl + warp * 8 + wl;

    const float rad = theta[t] * 0.017453292519943295f;
    float s, c;
    sincosf(rad, &s, &c);

    // Angle-adaptive layout: keep |row-coef wrt w| = min(|s|,|c|) <= 0.707
    float cA, sA, cB, sB;
    const float4* __restrict__ img;
    if (fabsf(s) > fabsf(c)) { cA = -s; sA = c; cB = c;  sB = s; img = g_imgT; }
    else                     { cA = c;  sA = s; cB = -s; sB = c; img = g_img;  }

    // col = cA*wf + sA*hf + 255.5 (+PAD folded in), row = cB*wf + sB*hf + 255.5 (+PAD)
    const float wf   = (float)w - 255.5f;
    const float colw = fmaf(cA, wf, 383.5f);
    const float roww = fmaf(cB, wf, 383.5f);
    float hf = (float)(ch * HCH + hl) - 255.5f;

    float4 acc = make_float4(0.f, 0.f, 0.f, 0.f);

    #pragma unroll 4
    for (int k = 0; k < HCH / 4; ++k) {
        const float colv = fmaf(sA, hf, colw);
        const float rowv = fmaf(sB, hf, roww);
        const float cf = floorf(colv);
        const float rf = floorf(rowv);
        const float fc = colv - cf;
        const float fr = rowv - rf;
        const int   ci = (int)cf;
        const int   ri = (int)rf;

        const float4* p = img + (ri * PW + ci);
        const float4 v00 = p[0];
        const float4 v01 = p[1];
        const float4 v10 = p[PW];
        const float4 v11 = p[PW + 1];

        const float gc = 1.f - fc, gr = 1.f - fr;
        const float w00 = gr * gc, w01 = gr * fc, w10 = fr * gc, w11 = fr * fc;

        acc.x = fmaf(v00.x, w00, acc.x); acc.x = fmaf(v01.x, w01, acc.x);
        acc.x = fmaf(v10.x, w10, acc.x); acc.x = fmaf(v11.x, w11, acc.x);
        acc.y = fmaf(v00.y, w00, acc.y); acc.y = fmaf(v01.y, w01, acc.y);
        acc.y = fmaf(v10.y, w10, acc.y); acc.y = fmaf(v11.y, w11, acc.y);
        acc.z = fmaf(v00.z, w00, acc.z); acc.z = fmaf(v01.z, w01, acc.z);
        acc.z = fmaf(v10.z, w10, acc.z); acc.z = fmaf(v11.z, w11, acc.z);
        acc.w = fmaf(v00.w, w00, acc.w); acc.w = fmaf(v01.w, w01, acc.w);
        acc.w = fmaf(v10.w, w10, acc.w); acc.w = fmaf(v11.w, w11, acc.w);

        hf += 4.0f;
    }

    // Reduce the 4 h-sublanes (lanes xor 8, xor 16)
    const unsigned m = 0xFFFFFFFFu;
    acc.x += __shfl_xor_sync(m, acc.x, 8);
    acc.y += __shfl_xor_sync(m, acc.y, 8);
    acc.z += __shfl_xor_sync(m, acc.z, 8);
    acc.w += __shfl_xor_sync(m, acc.w, 8);
    acc.x += __shfl_xor_sync(m, acc.x, 16);
    acc.y += __shfl_xor_sync(m, acc.y, 16);
    acc.z += __shfl_xor_sync(m, acc.z, 16);
    acc.w += __shfl_xor_sync(m, acc.w, 16);

    if (hl == 0) {
        g_partial[(ch * NT + t) * IW + w] = acc;
    }
}

// ---------------------------------------------------------------------------
// Reduce NCH partials -> output (n, 0, w, t) layout
// ---------------------------------------------------------------------------
__global__ void reduce_kernel(float* __restrict__ out) {
    int idx = blockIdx.x * blockDim.x + threadIdx.x;
    if (idx >= NB * IW * NT) return;
    const int t   = idx % NT;
    const int rem = idx / NT;
    const int w   = rem & (IW - 1);
    const int n   = rem >> 9;
    float sum = 0.f;
    #pragma unroll
    for (int ch = 0; ch < NCH; ++ch) {
        const float* p = (const float*)&g_partial[(ch * NT + t) * IW + w];
        sum += p[n];
    }
    out[idx] = sum;
}

// ---------------------------------------------------------------------------
extern "C" void kernel_launch(void* const* d_in, const int* in_sizes, int n_in,
                              void* d_out, int out_size) {
    const float* x  = (const float*)d_in[0];
    const float* th = (const float*)d_in[1];
    if (n_in >= 2 && in_sizes[0] == NT) {  // robust to input ordering
        const float* tmp = x; x = th; th = tmp;
    }
    float* out = (float*)d_out;

    prep_kernel<<<(PW * PW + 255) / 256, 256>>>(x);

    dim3 grid(NT, IW / 64, NCH);
    radon_kernel<<<grid, 256>>>(th);

    reduce_kernel<<<(NB * IW * NT + 255) / 256, 256>>>(out);
}

// round 3
// speedup vs baseline: 1.0260x; 1.0260x over previous
#include <cuda_runtime.h>

#define IW   512            // image width/height
#define NB   4              // batch
#define NT   180            // angles
#define PAD  128
#define PW   (IW + 2*PAD)   // 768 padded dim
#define NCH  4              // h-chunks
#define HCH  (IW / NCH)     // 128 h per chunk
#define IMG_STRIDE (IW*IW)  // 262144 floats per image

typedef unsigned long long u64;

// Scratch (static device memory: allowed; no allocations)
__device__ float4 g_img [PW * PW];   // padded, batch-packed image        (9.4 MB)
__device__ float4 g_imgT[PW * PW];   // padded, batch-packed transposed   (9.4 MB)
__device__ float4 g_partial[NCH * NT * IW];  // per-chunk partial sums    (5.9 MB)

// Packed fp32x2 helpers (Blackwell f32x2 pipe)
#define DUP2(d, f)      asm("mov.b64 %0, {%1, %1};" : "=l"(d) : "f"(f))
#define MUL2(d, a, b)   asm("mul.rn.f32x2 %0, %1, %2;" : "=l"(d) : "l"(a), "l"(b))
#define FMA2(acc, v, w) asm("fma.rn.f32x2 %0, %1, %2, %0;" : "+l"(acc) : "l"(v), "l"(w))

// ---------------------------------------------------------------------------
// Prep A: zero the padding borders of both images.
// ---------------------------------------------------------------------------
__global__ void prep_border_kernel() {
    int idx = blockIdx.x * blockDim.x + threadIdx.x;
    if (idx >= PW * PW) return;
    int row = idx / PW;
    int col = idx - row * PW;
    if ((unsigned)(row - PAD) < (unsigned)IW && (unsigned)(col - PAD) < (unsigned)IW)
        return;  // interior handled by fill kernel
    const float4 z = make_float4(0.f, 0.f, 0.f, 0.f);
    g_img [idx] = z;
    g_imgT[idx] = z;
}

// ---------------------------------------------------------------------------
// Prep B: fill interior. Read each pixel once (coalesced), write normal
// (coalesced) and transposed (scatter-write; writes don't stall).
// ---------------------------------------------------------------------------
__global__ void prep_fill_kernel(const float* __restrict__ x) {
    int idx = blockIdx.x * blockDim.x + threadIdx.x;
    if (idx >= IW * IW) return;
    int r = idx >> 9;          // /512
    int c = idx & (IW - 1);
    float4 v;
    v.x = x[idx];
    v.y = x[idx +     IMG_STRIDE];
    v.z = x[idx + 2 * IMG_STRIDE];
    v.w = x[idx + 3 * IMG_STRIDE];
    g_img [(r + PAD) * PW + (c + PAD)] = v;
    g_imgT[(c + PAD) * PW + (r + PAD)] = v;
}

// ---------------------------------------------------------------------------
// Radon: block = (theta, w-tile of 64, h-chunk of 128). 256 threads.
// Warp footprint: 8 w-lanes x 4 h-sublanes (dense rotated patch).
// Software-pipelined gather + packed f32x2 FMAs.
// ---------------------------------------------------------------------------
__global__ __launch_bounds__(256, 4) void radon_kernel(const float* __restrict__ theta) {
    const int t    = blockIdx.x;
    const int wtl  = blockIdx.y * 64;
    const int ch   = blockIdx.z;
    const int tid  = threadIdx.x;
    const int warp = tid >> 5;
    const int lane = tid & 31;
    const int wl   = lane & 7;   // w sub-lane
    const int hl   = lane >> 3;  // h sub-lane (0..3)
    const int w    = wtl + warp * 8 + wl;

    const float rad = theta[t] * 0.017453292519943295f;
    float s, c;
    sincosf(rad, &s, &c);

    // Angle-adaptive layout: keep |row-coef wrt w| = min(|s|,|c|) <= 0.707
    float cA, sA, cB, sB;
    const float4* __restrict__ img;
    if (fabsf(s) > fabsf(c)) { cA = -s; sA = c; cB = c;  sB = s; img = g_imgT; }
    else                     { cA = c;  sA = s; cB = -s; sB = c; img = g_img;  }

    // col = cA*wf + sA*hf + 255.5 (+PAD folded in), row = cB*wf + sB*hf + 255.5 (+PAD)
    const float wf   = (float)w - 255.5f;
    const float colw = fmaf(cA, wf, 383.5f);
    const float roww = fmaf(cB, wf, 383.5f);
    float hf = (float)(ch * HCH + hl) - 255.5f;

    // ---- pipeline prologue: loads for iteration 0 ----
    float colv = fmaf(sA, hf, colw);
    float rowv = fmaf(sB, hf, roww);
    float cf = floorf(colv);
    float rf = floorf(rowv);
    const float4* p = img + ((int)rf * PW + (int)cf);
    ulonglong2 v00 = *(const ulonglong2*)(p);
    ulonglong2 v01 = *(const ulonglong2*)(p + 1);
    ulonglong2 v10 = *(const ulonglong2*)(p + PW);
    ulonglong2 v11 = *(const ulonglong2*)(p + PW + 1);
    float fc = colv - cf;
    float fr = rowv - rf;

    u64 acc0 = 0ull, acc1 = 0ull;   // (b0,b1) and (b2,b3) packed fp32 pairs

    #pragma unroll 8
    for (int k = 0; k < HCH / 4; ++k) {
        // ---- issue next iteration's loads (one step ahead; always in-bounds
        // thanks to PAD=128: coords stay within [19,748] of the 768 grid) ----
        hf += 4.0f;
        const float colv2 = fmaf(sA, hf, colw);
        const float rowv2 = fmaf(sB, hf, roww);
        const float cf2 = floorf(colv2);
        const float rf2 = floorf(rowv2);
        const float4* p2 = img + ((int)rf2 * PW + (int)cf2);
        const ulonglong2 n00 = *(const ulonglong2*)(p2);
        const ulonglong2 n01 = *(const ulonglong2*)(p2 + 1);
        const ulonglong2 n10 = *(const ulonglong2*)(p2 + PW);
        const ulonglong2 n11 = *(const ulonglong2*)(p2 + PW + 1);

        // ---- bilinear accumulate for current iteration (packed f32x2) ----
        const float gc = 1.f - fc, gr = 1.f - fr;
        u64 GC, GR, FC, FR, W00, W01, W10, W11;
        DUP2(GC, gc); DUP2(GR, gr); DUP2(FC, fc); DUP2(FR, fr);
        MUL2(W00, GR, GC); MUL2(W01, GR, FC);
        MUL2(W10, FR, GC); MUL2(W11, FR, FC);
        FMA2(acc0, v00.x, W00); FMA2(acc1, v00.y, W00);
        FMA2(acc0, v01.x, W01); FMA2(acc1, v01.y, W01);
        FMA2(acc0, v10.x, W10); FMA2(acc1, v10.y, W10);
        FMA2(acc0, v11.x, W11); FMA2(acc1, v11.y, W11);

        // rotate pipeline registers
        v00 = n00; v01 = n01; v10 = n10; v11 = n11;
        fc = colv2 - cf2;
        fr = rowv2 - rf2;
    }

    // unpack packed accumulators -> 4 batch sums
    float ax, ay, az, aw;
    asm("mov.b64 {%0, %1}, %2;" : "=f"(ax), "=f"(ay) : "l"(acc0));
    asm("mov.b64 {%0, %1}, %2;" : "=f"(az), "=f"(aw) : "l"(acc1));

    // Reduce the 4 h-sublanes (lanes xor 8, xor 16)
    const unsigned m = 0xFFFFFFFFu;
    ax += __shfl_xor_sync(m, ax, 8);
    ay += __shfl_xor_sync(m, ay, 8);
    az += __shfl_xor_sync(m, az, 8);
    aw += __shfl_xor_sync(m, aw, 8);
    ax += __shfl_xor_sync(m, ax, 16);
    ay += __shfl_xor_sync(m, ay, 16);
    az += __shfl_xor_sync(m, az, 16);
    aw += __shfl_xor_sync(m, aw, 16);

    if (hl == 0) {
        g_partial[(ch * NT + t) * IW + w] = make_float4(ax, ay, az, aw);
    }
}

// ---------------------------------------------------------------------------
// Reduce NCH partials -> output (n, 0, w, t) layout
// ---------------------------------------------------------------------------
__global__ void reduce_kernel(float* __restrict__ out) {
    int idx = blockIdx.x * blockDim.x + threadIdx.x;
    if (idx >= NB * IW * NT) return;
    const int t   = idx % NT;
    const int rem = idx / NT;
    const int w   = rem & (IW - 1);
    const int n   = rem >> 9;
    float sum = 0.f;
    #pragma unroll
    for (int ch = 0; ch < NCH; ++ch) {
        const float* p = (const float*)&g_partial[(ch * NT + t) * IW + w];
        sum += p[n];
    }
    out[idx] = sum;
}

// ---------------------------------------------------------------------------
extern "C" void kernel_launch(void* const* d_in, const int* in_sizes, int n_in,
                              void* d_out, int out_size) {
    const float* x  = (const float*)d_in[0];
    const float* th = (const float*)d_in[1];
    if (n_in >= 2 && in_sizes[0] == NT) {  // robust to input ordering
        const float* tmp = x; x = th; th = tmp;
    }
    float* out = (float*)d_out;

    prep_border_kernel<<<(PW * PW + 255) / 256, 256>>>();
    prep_fill_kernel<<<(IW * IW + 255) / 256, 256>>>(x);

    dim3 grid(NT, IW / 64, NCH);
    radon_kernel<<<grid, 256>>>(th);

    reduce_kernel<<<(NB * IW * NT + 255) / 256, 256>>>(out);
}

// round 4
// speedup vs baseline: 1.4016x; 1.3660x over previous
#include <cuda_runtime.h>

#define IW   512            // image width/height
#define NB   4              // batch
#define NT   180            // output angles
#define NTH  90             // sampled angles (0..89); 90..179 via row sums
#define PAD  128
#define PW   (IW + 2*PAD)   // 768 padded dim
#define NCH  4              // h-chunks
#define HCH  (IW / NCH)     // 128 h per chunk
#define NWT  8              // w-tiles of 64
#define IMG_STRIDE (IW*IW)

// Scratch (static device memory: allowed; no allocations)
__device__ float4 g_img [PW * PW];             // padded batch-packed image
__device__ float4 g_imgT[PW * PW];             // transposed version
__device__ float4 g_colpart[NCH * NTH * IW];   // [ch][t][w]  column partials
__device__ float4 g_rowpart[NTH * NWT * IW];   // [t][wtile][h] row partials

// ---------------------------------------------------------------------------
// Prep A: zero the padding borders of both images.
// ---------------------------------------------------------------------------
__global__ void prep_border_kernel() {
    int idx = blockIdx.x * blockDim.x + threadIdx.x;
    if (idx >= PW * PW) return;
    int row = idx / PW;
    int col = idx - row * PW;
    if ((unsigned)(row - PAD) < (unsigned)IW && (unsigned)(col - PAD) < (unsigned)IW)
        return;
    const float4 z = make_float4(0.f, 0.f, 0.f, 0.f);
    g_img [idx] = z;
    g_imgT[idx] = z;
}

// ---------------------------------------------------------------------------
// Prep B: fill interior (coalesced reads, scatter-write transpose).
// ---------------------------------------------------------------------------
__global__ void prep_fill_kernel(const float* __restrict__ x) {
    int idx = blockIdx.x * blockDim.x + threadIdx.x;
    if (idx >= IW * IW) return;
    int r = idx >> 9;
    int c = idx & (IW - 1);
    float4 v;
    v.x = x[idx];
    v.y = x[idx +     IMG_STRIDE];
    v.z = x[idx + 2 * IMG_STRIDE];
    v.w = x[idx + 3 * IMG_STRIDE];
    g_img [(r + PAD) * PW + (c + PAD)] = v;
    g_imgT[(c + PAD) * PW + (r + PAD)] = v;
}

// ---------------------------------------------------------------------------
// Radon for t in 0..89; accumulates BOTH column sums (-> P_t) and row sums
// (-> P_{t+90} mirrored). Warp footprint: 8 w-lanes x 4 h-sublanes.
// ---------------------------------------------------------------------------
__global__ __launch_bounds__(256) void radon_kernel(const float* __restrict__ theta) {
    __shared__ float4 s_row[8][HCH][2];   // [warp][h_local][half] = 32KB

    const int t    = blockIdx.x;          // 0..89
    const int wt   = blockIdx.y;          // 0..7
    const int ch   = blockIdx.z;          // 0..3
    const int tid  = threadIdx.x;
    const int warp = tid >> 5;
    const int lane = tid & 31;
    const int wl   = lane & 7;
    const int hl   = lane >> 3;
    const int w    = wt * 64 + warp * 8 + wl;

    const float rad = theta[t] * 0.017453292519943295f;
    float s, c;
    sincosf(rad, &s, &c);

    // Angle-adaptive layout: row-coefficient wrt w kept <= 0.707
    float cA, sA, cB, sB;
    const float4* __restrict__ img;
    if (fabsf(s) > fabsf(c)) { cA = -s; sA = c; cB = c;  sB = s; img = g_imgT; }
    else                     { cA = c;  sA = s; cB = -s; sB = c; img = g_img;  }

    const float wf   = (float)w - 255.5f;
    const float colw = fmaf(cA, wf, 383.5f);   // +PAD folded in
    const float roww = fmaf(cB, wf, 383.5f);
    float hf = (float)(ch * HCH + hl) - 255.5f;

    // pipeline prologue
    float colv = fmaf(sA, hf, colw);
    float rowv = fmaf(sB, hf, roww);
    float cf = floorf(colv), rf = floorf(rowv);
    const float4* p = img + ((int)rf * PW + (int)cf);
    float4 a00 = p[0], a01 = p[1], a10 = p[PW], a11 = p[PW + 1];
    float fc = colv - cf, fr = rowv - rf;

    float acc0 = 0.f, acc1 = 0.f, acc2 = 0.f, acc3 = 0.f;
    const unsigned m = 0xFFFFFFFFu;

    #pragma unroll 4
    for (int k = 0; k < HCH / 4; ++k) {
        // next iteration's loads (always in-bounds: PAD=128)
        hf += 4.0f;
        const float colv2 = fmaf(sA, hf, colw);
        const float rowv2 = fmaf(sB, hf, roww);
        const float cf2 = floorf(colv2), rf2 = floorf(rowv2);
        const float4* p2 = img + ((int)rf2 * PW + (int)cf2);
        const float4 n00 = p2[0], n01 = p2[1], n10 = p2[PW], n11 = p2[PW + 1];

        // bilinear sample value (per batch)
        const float gc = 1.f - fc, gr = 1.f - fr;
        const float w00 = gr * gc, w01 = gr * fc, w10 = fr * gc, w11 = fr * fc;
        float vx = fmaf(a00.x, w00, fmaf(a01.x, w01, fmaf(a10.x, w10, a11.x * w11)));
        float vy = fmaf(a00.y, w00, fmaf(a01.y, w01, fmaf(a10.y, w10, a11.y * w11)));
        float vz = fmaf(a00.z, w00, fmaf(a01.z, w01, fmaf(a10.z, w10, a11.z * w11)));
        float vw = fmaf(a00.w, w00, fmaf(a01.w, w01, fmaf(a10.w, w10, a11.w * w11)));

        // column accumulation (-> P_t)
        acc0 += vx; acc1 += vy; acc2 += vz; acc3 += vw;

        // partial row reduction over w-lanes (2 levels; halves stored to smem)
        vx += __shfl_xor_sync(m, vx, 1); vy += __shfl_xor_sync(m, vy, 1);
        vz += __shfl_xor_sync(m, vz, 1); vw += __shfl_xor_sync(m, vw, 1);
        vx += __shfl_xor_sync(m, vx, 2); vy += __shfl_xor_sync(m, vy, 2);
        vz += __shfl_xor_sync(m, vz, 2); vw += __shfl_xor_sync(m, vw, 2);
        if ((wl & 3) == 0)
            s_row[warp][hl + 4 * k][wl >> 2] = make_float4(vx, vy, vz, vw);

        // rotate pipeline
        a00 = n00; a01 = n01; a10 = n10; a11 = n11;
        fc = colv2 - cf2;
        fr = rowv2 - rf2;
    }

    // column partial: reduce over the 4 h-sublanes
    acc0 += __shfl_xor_sync(m, acc0, 8);  acc1 += __shfl_xor_sync(m, acc1, 8);
    acc2 += __shfl_xor_sync(m, acc2, 8);  acc3 += __shfl_xor_sync(m, acc3, 8);
    acc0 += __shfl_xor_sync(m, acc0, 16); acc1 += __shfl_xor_sync(m, acc1, 16);
    acc2 += __shfl_xor_sync(m, acc2, 16); acc3 += __shfl_xor_sync(m, acc3, 16);
    if (hl == 0)
        g_colpart[(ch * NTH + t) * IW + w] = make_float4(acc0, acc1, acc2, acc3);

    // row partial tail: combine 8 warps x 2 halves per h
    __syncthreads();
    if (tid < HCH) {
        float4 sum = make_float4(0.f, 0.f, 0.f, 0.f);
        #pragma unroll
        for (int wp = 0; wp < 8; ++wp) {
            #pragma unroll
            for (int half = 0; half < 2; ++half) {
                float4 v = s_row[wp][tid][half];
                sum.x += v.x; sum.y += v.y; sum.z += v.z; sum.w += v.w;
            }
        }
        g_rowpart[(t * NWT + wt) * IW + ch * HCH + tid] = sum;
    }
}

// ---------------------------------------------------------------------------
// Reduce: t<90 from column partials; t>=90 from row partials (mirrored).
// Thread map w-fastest so partial loads coalesce.
// ---------------------------------------------------------------------------
__global__ void reduce_kernel(float* __restrict__ out) {
    int idx = blockIdx.x * blockDim.x + threadIdx.x;   // n*(NT*IW) + t*IW + w
    if (idx >= NB * NT * IW) return;
    const int w  = idx & (IW - 1);
    const int nt = idx >> 9;
    const int t  = nt % NT;
    const int n  = nt / NT;

    float sum = 0.f;
    if (t < NTH) {
        #pragma unroll
        for (int ch = 0; ch < NCH; ++ch)
            sum += ((const float*)&g_colpart[(ch * NTH + t) * IW + w])[n];
    } else {
        const int th = t - NTH;
        const int h  = IW - 1 - w;
        #pragma unroll
        for (int wt = 0; wt < NWT; ++wt)
            sum += ((const float*)&g_rowpart[(th * NWT + wt) * IW + h])[n];
    }
    out[n * (IW * NT) + w * NT + t] = sum;
}

// ---------------------------------------------------------------------------
extern "C" void kernel_launch(void* const* d_in, const int* in_sizes, int n_in,
                              void* d_out, int out_size) {
    const float* x  = (const float*)d_in[0];
    const float* th = (const float*)d_in[1];
    if (n_in >= 2 && in_sizes[0] == NT) {
        const float* tmp = x; x = th; th = tmp;
    }
    float* out = (float*)d_out;

    prep_border_kernel<<<(PW * PW + 255) / 256, 256>>>();
    prep_fill_kernel<<<(IW * IW + 255) / 256, 256>>>(x);

    dim3 grid(NTH, NWT, NCH);
    radon_kernel<<<grid, 256>>>(th);

    reduce_kernel<<<(NB * NT * IW + 255) / 256, 256>>>(out);
}

// round 5
// speedup vs baseline: 1.7906x; 1.2775x over previous
#include <cuda_runtime.h>
#include <cuda_fp16.h>

#define IW   512
#define NB   4
#define NT   180
#define NTH  90             // sampled angles; 90..179 via row sums
#define PAD  128
#define PW   (IW + 2*PAD)   // 768
#define NCH  4
#define HCH  (IW / NCH)     // 128
#define NWT  8
#define IMG_STRIDE (IW*IW)

// Scratch (static device memory; no allocations)
__device__ uint2 g_img [PW * PW];                  // half4 pixels, padded
__device__ uint2 g_imgT[PW * PW];                  // transposed
__device__ float g_colpart[NB][NCH][NTH][IW];      // SoA column partials
__device__ float g_rowpart[NB][NTH][NWT][IW];      // SoA row partials

// ---------------------------------------------------------------------------
__global__ void prep_border_kernel() {
    int idx = blockIdx.x * blockDim.x + threadIdx.x;
    if (idx >= PW * PW) return;
    int row = idx / PW;
    int col = idx - row * PW;
    if ((unsigned)(row - PAD) < (unsigned)IW && (unsigned)(col - PAD) < (unsigned)IW)
        return;
    const uint2 z = make_uint2(0u, 0u);
    g_img [idx] = z;
    g_imgT[idx] = z;
}

// ---------------------------------------------------------------------------
__global__ void prep_fill_kernel(const float* __restrict__ x) {
    int idx = blockIdx.x * blockDim.x + threadIdx.x;
    if (idx >= IW * IW) return;
    int r = idx >> 9;
    int c = idx & (IW - 1);
    __half2 lo = __floats2half2_rn(x[idx],                x[idx +     IMG_STRIDE]);
    __half2 hi = __floats2half2_rn(x[idx + 2*IMG_STRIDE], x[idx + 3 * IMG_STRIDE]);
    uint2 v;
    v.x = *(const unsigned int*)&lo;
    v.y = *(const unsigned int*)&hi;
    g_img [(r + PAD) * PW + (c + PAD)] = v;
    g_imgT[(c + PAD) * PW + (r + PAD)] = v;
}

// ---------------------------------------------------------------------------
// Radon for t in 0..89; column sums -> P_t, row sums -> P_{t+90} (mirrored).
// half4 pixels, software-pipelined gather, valid-k clamping.
// ---------------------------------------------------------------------------
__global__ __launch_bounds__(256) void radon_kernel(const float* __restrict__ theta) {
    __shared__ float4 s_row[8][HCH][2];   // 32 KB

    const int t    = blockIdx.x;
    const int wt   = blockIdx.y;
    const int ch   = blockIdx.z;
    const int tid  = threadIdx.x;
    const int warp = tid >> 5;
    const int lane = tid & 31;
    const int wl   = lane & 7;
    const int hl   = lane >> 3;
    const int w    = wt * 64 + warp * 8 + wl;

    // zero row-partial slab (skipped k's must read as 0)
    {
        float4* sr = &s_row[0][0][0];
        #pragma unroll
        for (int i = 0; i < 8; ++i)
            sr[tid + 256 * i] = make_float4(0.f, 0.f, 0.f, 0.f);
    }
    __syncthreads();

    const float rad = theta[t] * 0.017453292519943295f;
    float s, c;
    sincosf(rad, &s, &c);

    // Angle-adaptive layout: |sA| = min(|s|,|c|) <= 0.707, sB = max >= 0.707 (>0)
    float cA, sA, cB, sB;
    const uint2* __restrict__ img;
    if (fabsf(s) > fabsf(c)) { cA = -s; sA = c; cB = c;  sB = s; img = g_imgT; }
    else                     { cA = c;  sA = s; cB = -s; sB = c; img = g_img;  }

    const float wf    = (float)w - 255.5f;
    const float colw  = fmaf(cA, wf, 383.5f);
    const float roww  = fmaf(cB, wf, 383.5f);
    const float hbase = (float)(ch * HCH) - 255.5f;

    // ---- warp-uniform valid-k interval (data rows/cols are [128,639];
    //      nonzero bilinear support is coord in [127, 640)) ----
    const float wfa = (float)(wt * 64 + warp * 8) - 255.5f;
    const float wfb = wfa + 7.0f;
    float t1a = cB * wfa, t1b = cB * wfb;
    const float rA = 383.5f + fminf(t1a, t1b);                  // row lower base
    const float rB = 383.5f + fmaxf(t1a, t1b) + 3.0f * sB;      // row upper base
    const float rh = sB * hbase;
    const float inv4sB = 1.0f / (4.0f * sB);
    float kL = (127.0f - rB - rh) * inv4sB;
    float kU = (641.0f - rA - rh) * inv4sB;
    float t2a = cA * wfa, t2b = cA * wfb;
    const float cC = 383.5f + fminf(t2a, t2b) + fminf(0.f, 3.f * sA);
    const float cD = 383.5f + fmaxf(t2a, t2b) + fmaxf(0.f, 3.f * sA);
    if (sA > 0.01f) {
        const float inv = 1.0f / (4.0f * sA);
        kL = fmaxf(kL, (127.0f - cD - sA * hbase) * inv);
        kU = fminf(kU, (641.0f - cC - sA * hbase) * inv);
    } else if (sA < -0.01f) {
        const float inv = 1.0f / (4.0f * sA);
        kL = fmaxf(kL, (641.0f - cC - sA * hbase) * inv);
        kU = fminf(kU, (127.0f - cD - sA * hbase) * inv);
    }
    const int k0 = max(0, (int)floorf(kL) - 1);
    const int k1 = min(HCH / 4, (int)floorf(kU) + 2);

    float acc0 = 0.f, acc1 = 0.f, acc2 = 0.f, acc3 = 0.f;
    const unsigned m = 0xFFFFFFFFu;

    if (k0 < k1) {
        float hf = hbase + (float)hl + 4.0f * (float)k0;

        // pipeline prologue (all addresses in-bounds: rotation norm-preserving)
        float colv = fmaf(sA, hf, colw);
        float rowv = fmaf(sB, hf, roww);
        float cf = floorf(colv), rf = floorf(rowv);
        const uint2* p = img + ((int)rf * PW + (int)cf);
        uint2 q00 = p[0], q01 = p[1], q10 = p[PW], q11 = p[PW + 1];
        float fc = colv - cf, fr = rowv - rf;

        for (int k = k0; k < k1; ++k) {
            // prefetch next iteration
            hf += 4.0f;
            const float colv2 = fmaf(sA, hf, colw);
            const float rowv2 = fmaf(sB, hf, roww);
            const float cf2 = floorf(colv2), rf2 = floorf(rowv2);
            const uint2* p2 = img + ((int)rf2 * PW + (int)cf2);
            const uint2 n00 = p2[0], n01 = p2[1], n10 = p2[PW], n11 = p2[PW + 1];

            // bilinear in fp32 (convert half pixels)
            const float gc = 1.f - fc, gr = 1.f - fr;
            const float w00 = gr * gc, w01 = gr * fc, w10 = fr * gc, w11 = fr * fc;
            const float2 a00 = __half22float2(*(const __half2*)&q00.x);
            const float2 b00 = __half22float2(*(const __half2*)&q00.y);
            const float2 a01 = __half22float2(*(const __half2*)&q01.x);
            const float2 b01 = __half22float2(*(const __half2*)&q01.y);
            const float2 a10 = __half22float2(*(const __half2*)&q10.x);
            const float2 b10 = __half22float2(*(const __half2*)&q10.y);
            const float2 a11 = __half22float2(*(const __half2*)&q11.x);
            const float2 b11 = __half22float2(*(const __half2*)&q11.y);

            float vx = fmaf(a00.x, w00, fmaf(a01.x, w01, fmaf(a10.x, w10, a11.x * w11)));
            float vy = fmaf(a00.y, w00, fmaf(a01.y, w01, fmaf(a10.y, w10, a11.y * w11)));
            float vz = fmaf(b00.x, w00, fmaf(b01.x, w01, fmaf(b10.x, w10, b11.x * w11)));
            float vw = fmaf(b00.y, w00, fmaf(b01.y, w01, fmaf(b10.y, w10, b11.y * w11)));

            // column accumulation (-> P_t)
            acc0 += vx; acc1 += vy; acc2 += vz; acc3 += vw;

            // partial row reduction over w-lanes
            vx += __shfl_xor_sync(m, vx, 1); vy += __shfl_xor_sync(m, vy, 1);
            vz += __shfl_xor_sync(m, vz, 1); vw += __shfl_xor_sync(m, vw, 1);
            vx += __shfl_xor_sync(m, vx, 2); vy += __shfl_xor_sync(m, vy, 2);
            vz += __shfl_xor_sync(m, vz, 2); vw += __shfl_xor_sync(m, vw, 2);
            if ((wl & 3) == 0)
                s_row[warp][hl + 4 * k][wl >> 2] = make_float4(vx, vy, vz, vw);

            // rotate pipeline
            q00 = n00; q01 = n01; q10 = n10; q11 = n11;
            fc = colv2 - cf2;
            fr = rowv2 - rf2;
        }
    }

    // column partial: reduce 4 h-sublanes
    acc0 += __shfl_xor_sync(m, acc0, 8);  acc1 += __shfl_xor_sync(m, acc1, 8);
    acc2 += __shfl_xor_sync(m, acc2, 8);  acc3 += __shfl_xor_sync(m, acc3, 8);
    acc0 += __shfl_xor_sync(m, acc0, 16); acc1 += __shfl_xor_sync(m, acc1, 16);
    acc2 += __shfl_xor_sync(m, acc2, 16); acc3 += __shfl_xor_sync(m, acc3, 16);
    if (hl == 0) {
        g_colpart[0][ch][t][w] = acc0;
        g_colpart[1][ch][t][w] = acc1;
        g_colpart[2][ch][t][w] = acc2;
        g_colpart[3][ch][t][w] = acc3;
    }

    // row partial tail
    __syncthreads();
    if (tid < HCH) {
        float4 sum = make_float4(0.f, 0.f, 0.f, 0.f);
        #pragma unroll
        for (int wp = 0; wp < 8; ++wp) {
            #pragma unroll
            for (int half = 0; half < 2; ++half) {
                float4 v = s_row[wp][tid][half];
                sum.x += v.x; sum.y += v.y; sum.z += v.z; sum.w += v.w;
            }
        }
        const int h = ch * HCH + tid;
        g_rowpart[0][t][wt][h] = sum.x;
        g_rowpart[1][t][wt][h] = sum.y;
        g_rowpart[2][t][wt][h] = sum.z;
        g_rowpart[3][t][wt][h] = sum.w;
    }
}

// ---------------------------------------------------------------------------
// Reduce: t<90 from column partials; t>=90 from row partials (mirrored).
// ---------------------------------------------------------------------------
__global__ void reduce_kernel(float* __restrict__ out) {
    int idx = blockIdx.x * blockDim.x + threadIdx.x;   // [n][t][w], w fastest
    if (idx >= NB * NT * IW) return;
    const int w  = idx & (IW - 1);
    const int nt = idx >> 9;
    const int t  = nt % NT;
    const int n  = nt / NT;

    float sum = 0.f;
    if (t < NTH) {
        #pragma unroll
        for (int ch = 0; ch < NCH; ++ch)
            sum += g_colpart[n][ch][t][w];
    } else {
        const int th = t - NTH;
        const int h  = IW - 1 - w;
        #pragma unroll
        for (int wt = 0; wt < NWT; ++wt)
            sum += g_rowpart[n][th][wt][h];
    }
    out[n * (IW * NT) + w * NT + t] = sum;
}

// ---------------------------------------------------------------------------
extern "C" void kernel_launch(void* const* d_in, const int* in_sizes, int n_in,
                              void* d_out, int out_size) {
    const float* x  = (const float*)d_in[0];
    const float* th = (const float*)d_in[1];
    if (n_in >= 2 && in_sizes[0] == NT) {
        const float* tmp = x; x = th; th = tmp;
    }
    float* out = (float*)d_out;

    prep_border_kernel<<<(PW * PW + 255) / 256, 256>>>();
    prep_fill_kernel<<<(IW * IW + 255) / 256, 256>>>(x);

    dim3 grid(NTH, NWT, NCH);
    radon_kernel<<<grid, 256>>>(th);

    reduce_kernel<<<(NB * NT * IW + 255) / 256, 256>>>(out);
}

// round 6
// speedup vs baseline: 2.1535x; 1.2027x over previous
#include <cuda_runtime.h>
#include <cuda_fp16.h>

#define IW   512
#define NB   4
#define NT   180
#define NTH  90             // sampled angles; 90..179 via row sums
#define PAD  128
#define PW   (IW + 2*PAD)   // 768
#define NCH  4
#define HCH  (IW / NCH)     // 128
#define NWT  8
#define IMG_STRIDE (IW*IW)

// Scratch (static device memory; no allocations)
// Pair entry at (r,c): 4 x __half2 = 16B, one half2 per batch = (pix[r][c], pix[r][c+1])
__device__ uint4 g_pair [PW * PW];                 // normal orientation (18.9MB total w/ T)
__device__ uint4 g_pairT[PW * PW];                 // transposed orientation
__device__ float g_colpart[NB][NCH][NTH][IW];      // SoA column partials
__device__ float g_rowpart[NB][NTH][NWT][IW];      // SoA row partials

// ---------------------------------------------------------------------------
// Zero everything outside the nonzero-entry rect rows[PAD,PAD+IW) x cols[PAD-1,PAD+IW)
// ---------------------------------------------------------------------------
__global__ void prep_border_kernel() {
    int idx = blockIdx.x * blockDim.x + threadIdx.x;
    if (idx >= PW * PW) return;
    int row = idx / PW;
    int col = idx - row * PW;
    if ((unsigned)(row - PAD) < (unsigned)IW &&
        (unsigned)(col - (PAD - 1)) < (unsigned)(IW + 1))
        return;  // interior rect handled by fill kernels
    const uint4 z = make_uint4(0u, 0u, 0u, 0u);
    g_pair [idx] = z;
    g_pairT[idx] = z;
}

// ---------------------------------------------------------------------------
// Fill normal pair image: entry(r, cc) = (x[r][cc], x[r][cc+1]) clamped, cc in [-1, IW)
// Coalesced reads (c fastest).
// ---------------------------------------------------------------------------
__global__ void prep_fill_kernel(const float* __restrict__ x) {
    int idx = blockIdx.x * blockDim.x + threadIdx.x;
    if (idx >= IW * (IW + 1)) return;
    const int r  = idx / (IW + 1);
    const int cc = idx - r * (IW + 1) - 1;         // -1 .. IW-1
    const int oL = r * IW + cc;
    const int oR = oL + 1;
    const bool okL = (cc >= 0);
    const bool okR = (cc + 1 < IW);
    uint4 e;
    #pragma unroll
    for (int b = 0; b < 4; ++b) {
        float l = okL ? x[oL + b * IMG_STRIDE] : 0.f;
        float rr = okR ? x[oR + b * IMG_STRIDE] : 0.f;
        __half2 h = __floats2half2_rn(l, rr);
        ((unsigned int*)&e)[b] = *(const unsigned int*)&h;
    }
    g_pair[(r + PAD) * PW + (cc + PAD)] = e;
}

// ---------------------------------------------------------------------------
// Fill transposed pair image: entryT(c, rr) = (x[rr][c], x[rr+1][c]) clamped.
// Threads: c fastest -> coalesced reads; scatter writes.
// ---------------------------------------------------------------------------
__global__ void prep_fillT_kernel(const float* __restrict__ x) {
    int idx = blockIdx.x * blockDim.x + threadIdx.x;
    if (idx >= IW * (IW + 1)) return;
    const int rr = idx / IW - 1;                   // -1 .. IW-1
    const int c  = idx - (rr + 1) * IW;
    const int oT = rr * IW + c;
    const int oB = oT + IW;
    const bool okT = (rr >= 0);
    const bool okB = (rr + 1 < IW);
    uint4 e;
    #pragma unroll
    for (int b = 0; b < 4; ++b) {
        float tv = okT ? x[oT + b * IMG_STRIDE] : 0.f;
        float bv = okB ? x[oB + b * IMG_STRIDE] : 0.f;
        __half2 h = __floats2half2_rn(tv, bv);
        ((unsigned int*)&e)[b] = *(const unsigned int*)&h;
    }
    g_pairT[(c + PAD) * PW + (rr + PAD)] = e;
}

// ---------------------------------------------------------------------------
// Radon for t in 0..89; column sums -> P_t, row sums -> P_{t+90} (mirrored).
// Pair-packed fp16 pixels: 2 LDG.128 per bilinear sample.
// ---------------------------------------------------------------------------
__global__ __launch_bounds__(256) void radon_kernel(const float* __restrict__ theta) {
    __shared__ float4 s_row[8][HCH][2];   // 32 KB

    const int t    = blockIdx.x;
    const int wt   = blockIdx.y;
    const int ch   = blockIdx.z;
    const int tid  = threadIdx.x;
    const int warp = tid >> 5;
    const int lane = tid & 31;
    const int wl   = lane & 7;
    const int hl   = lane >> 3;
    const int w    = wt * 64 + warp * 8 + wl;

    // zero row-partial slab (skipped k's must read as 0)
    {
        float4* sr = &s_row[0][0][0];
        #pragma unroll
        for (int i = 0; i < 8; ++i)
            sr[tid + 256 * i] = make_float4(0.f, 0.f, 0.f, 0.f);
    }
    __syncthreads();

    const float rad = theta[t] * 0.017453292519943295f;
    float s, c;
    sincosf(rad, &s, &c);

    // Angle-adaptive layout: |sA| = min <= 0.707, sB = max >= 0.707 (>0)
    float cA, sA, cB, sB;
    const uint4* __restrict__ img;
    if (fabsf(s) > fabsf(c)) { cA = -s; sA = c; cB = c;  sB = s; img = g_pairT; }
    else                     { cA = c;  sA = s; cB = -s; sB = c; img = g_pair;  }

    const float wf    = (float)w - 255.5f;
    const float colw  = fmaf(cA, wf, 383.5f);
    const float roww  = fmaf(cB, wf, 383.5f);
    const float hbase = (float)(ch * HCH) - 255.5f;

    // warp-uniform valid-k interval (nonzero bilinear support: coord in [127,640))
    const float wfa = (float)(wt * 64 + warp * 8) - 255.5f;
    const float wfb = wfa + 7.0f;
    float t1a = cB * wfa, t1b = cB * wfb;
    const float rA = 383.5f + fminf(t1a, t1b);
    const float rB = 383.5f + fmaxf(t1a, t1b) + 3.0f * sB;
    const float rh = sB * hbase;
    const float inv4sB = 1.0f / (4.0f * sB);
    float kL = (127.0f - rB - rh) * inv4sB;
    float kU = (641.0f - rA - rh) * inv4sB;
    float t2a = cA * wfa, t2b = cA * wfb;
    const float cC = 383.5f + fminf(t2a, t2b) + fminf(0.f, 3.f * sA);
    const float cD = 383.5f + fmaxf(t2a, t2b) + fmaxf(0.f, 3.f * sA);
    if (sA > 0.01f) {
        const float inv = 1.0f / (4.0f * sA);
        kL = fmaxf(kL, (127.0f - cD - sA * hbase) * inv);
        kU = fminf(kU, (641.0f - cC - sA * hbase) * inv);
    } else if (sA < -0.01f) {
        const float inv = 1.0f / (4.0f * sA);
        kL = fmaxf(kL, (641.0f - cC - sA * hbase) * inv);
        kU = fminf(kU, (127.0f - cD - sA * hbase) * inv);
    }
    const int k0 = max(0, (int)floorf(kL) - 1);
    const int k1 = min(HCH / 4, (int)floorf(kU) + 2);

    float acc0 = 0.f, acc1 = 0.f, acc2 = 0.f, acc3 = 0.f;
    const unsigned m = 0xFFFFFFFFu;

    if (k0 < k1) {
        float hf = hbase + (float)hl + 4.0f * (float)k0;

        // pipeline prologue
        float colv = fmaf(sA, hf, colw);
        float rowv = fmaf(sB, hf, roww);
        float cf = floorf(colv), rf = floorf(rowv);
        const uint4* p = img + ((int)rf * PW + (int)cf);
        uint4 qT = p[0];          // top pair: (v00, v01) x 4 batches
        uint4 qB = p[PW];         // bottom pair: (v10, v11) x 4 batches
        float fc = colv - cf, fr = rowv - rf;

        for (int k = k0; k < k1; ++k) {
            // prefetch next iteration (always in-bounds: PAD=128)
            hf += 4.0f;
            const float colv2 = fmaf(sA, hf, colw);
            const float rowv2 = fmaf(sB, hf, roww);
            const float cf2 = floorf(colv2), rf2 = floorf(rowv2);
            const uint4* p2 = img + ((int)rf2 * PW + (int)cf2);
            const uint4 nT = p2[0], nB = p2[PW];

            // bilinear in fp32
            const float gc = 1.f - fc, gr = 1.f - fr;
            const float w00 = gr * gc, w01 = gr * fc, w10 = fr * gc, w11 = fr * fc;
            const float2 t0 = __half22float2(*(const __half2*)&qT.x);
            const float2 t1 = __half22float2(*(const __half2*)&qT.y);
            const float2 t2 = __half22float2(*(const __half2*)&qT.z);
            const float2 t3 = __half22float2(*(const __half2*)&qT.w);
            const float2 b0 = __half22float2(*(const __half2*)&qB.x);
            const float2 b1 = __half22float2(*(const __half2*)&qB.y);
            const float2 b2 = __half22float2(*(const __half2*)&qB.z);
            const float2 b3 = __half22float2(*(const __half2*)&qB.w);

            float vx = fmaf(t0.x, w00, fmaf(t0.y, w01, fmaf(b0.x, w10, b0.y * w11)));
            float vy = fmaf(t1.x, w00, fmaf(t1.y, w01, fmaf(b1.x, w10, b1.y * w11)));
            float vz = fmaf(t2.x, w00, fmaf(t2.y, w01, fmaf(b2.x, w10, b2.y * w11)));
            float vw = fmaf(t3.x, w00, fmaf(t3.y, w01, fmaf(b3.x, w10, b3.y * w11)));

            // column accumulation (-> P_t)
            acc0 += vx; acc1 += vy; acc2 += vz; acc3 += vw;

            // partial row reduction over w-lanes
            vx += __shfl_xor_sync(m, vx, 1); vy += __shfl_xor_sync(m, vy, 1);
            vz += __shfl_xor_sync(m, vz, 1); vw += __shfl_xor_sync(m, vw, 1);
            vx += __shfl_xor_sync(m, vx, 2); vy += __shfl_xor_sync(m, vy, 2);
            vz += __shfl_xor_sync(m, vz, 2); vw += __shfl_xor_sync(m, vw, 2);
            if ((wl & 3) == 0)
                s_row[warp][hl + 4 * k][wl >> 2] = make_float4(vx, vy, vz, vw);

            // rotate pipeline
            qT = nT; qB = nB;
            fc = colv2 - cf2;
            fr = rowv2 - rf2;
        }
    }

    // column partial: reduce 4 h-sublanes
    acc0 += __shfl_xor_sync(m, acc0, 8);  acc1 += __shfl_xor_sync(m, acc1, 8);
    acc2 += __shfl_xor_sync(m, acc2, 8);  acc3 += __shfl_xor_sync(m, acc3, 8);
    acc0 += __shfl_xor_sync(m, acc0, 16); acc1 += __shfl_xor_sync(m, acc1, 16);
    acc2 += __shfl_xor_sync(m, acc2, 16); acc3 += __shfl_xor_sync(m, acc3, 16);
    if (hl == 0) {
        g_colpart[0][ch][t][w] = acc0;
        g_colpart[1][ch][t][w] = acc1;
        g_colpart[2][ch][t][w] = acc2;
        g_colpart[3][ch][t][w] = acc3;
    }

    // row partial tail
    __syncthreads();
    if (tid < HCH) {
        float4 sum = make_float4(0.f, 0.f, 0.f, 0.f);
        #pragma unroll
        for (int wp = 0; wp < 8; ++wp) {
            #pragma unroll
            for (int half = 0; half < 2; ++half) {
                float4 v = s_row[wp][tid][half];
                sum.x += v.x; sum.y += v.y; sum.z += v.z; sum.w += v.w;
            }
        }
        const int h = ch * HCH + tid;
        g_rowpart[0][t][wt][h] = sum.x;
        g_rowpart[1][t][wt][h] = sum.y;
        g_rowpart[2][t][wt][h] = sum.z;
        g_rowpart[3][t][wt][h] = sum.w;
    }
}

// ---------------------------------------------------------------------------
// Reduce: t<90 from column partials; t>=90 from row partials (mirrored).
// ---------------------------------------------------------------------------
__global__ void reduce_kernel(float* __restrict__ out) {
    int idx = blockIdx.x * blockDim.x + threadIdx.x;   // [n][t][w], w fastest
    if (idx >= NB * NT * IW) return;
    const int w  = idx & (IW - 1);
    const int nt = idx >> 9;
    const int t  = nt % NT;
    const int n  = nt / NT;

    float sum = 0.f;
    if (t < NTH) {
        #pragma unroll
        for (int ch = 0; ch < NCH; ++ch)
            sum += g_colpart[n][ch][t][w];
    } else {
        const int th = t - NTH;
        const int h  = IW - 1 - w;
        #pragma unroll
        for (int wt = 0; wt < NWT; ++wt)
            sum += g_rowpart[n][th][wt][h];
    }
    out[n * (IW * NT) + w * NT + t] = sum;
}

// ---------------------------------------------------------------------------
extern "C" void kernel_launch(void* const* d_in, const int* in_sizes, int n_in,
                              void* d_out, int out_size) {
    const float* x  = (const float*)d_in[0];
    const float* th = (const float*)d_in[1];
    if (n_in >= 2 && in_sizes[0] == NT) {
        const float* tmp = x; x = th; th = tmp;
    }
    float* out = (float*)d_out;

    prep_border_kernel<<<(PW * PW + 255) / 256, 256>>>();
    prep_fill_kernel <<<(IW * (IW + 1) + 255) / 256, 256>>>(x);
    prep_fillT_kernel<<<(IW * (IW + 1) + 255) / 256, 256>>>(x);

    dim3 grid(NTH, NWT, NCH);
    radon_kernel<<<grid, 256>>>(th);

    reduce_kernel<<<(NB * NT * IW + 255) / 256, 256>>>(out);
}

// round 8
// speedup vs baseline: 2.4622x; 1.1433x over previous
#include <cuda_runtime.h>
#include <cuda_fp16.h>

#define IW   512
#define NB   4
#define NT   180
#define NTH  90             // sampled angles; 90..179 via row sums
#define PAD  128
#define PW   (IW + 2*PAD)   // 768
#define NCH  4
#define HCH  (IW / NCH)     // 128
#define NWT  8
#define IMG_STRIDE (IW*IW)

// Pair entry at (r,c): 4 x __half2 = 16B = (pix[r][c], pix[r][c+1]) per batch
__device__ uint4 g_pair [PW * PW];
__device__ uint4 g_pairT[PW * PW];
__device__ float g_colpart[NB][NCH][NTH][IW];
__device__ float g_rowpart[NB][NTH][NWT][IW];

// ---------------------------------------------------------------------------
__global__ void prep_border_kernel() {
    int idx = blockIdx.x * blockDim.x + threadIdx.x;
    if (idx >= PW * PW) return;
    int row = idx / PW;
    int col = idx - row * PW;
    if ((unsigned)(row - PAD) < (unsigned)IW &&
        (unsigned)(col - (PAD - 1)) < (unsigned)(IW + 1))
        return;
    const uint4 z = make_uint4(0u, 0u, 0u, 0u);
    g_pair [idx] = z;
    g_pairT[idx] = z;
}

// ---------------------------------------------------------------------------
__global__ void prep_fill_kernel(const float* __restrict__ x) {
    int idx = blockIdx.x * blockDim.x + threadIdx.x;
    if (idx >= IW * (IW + 1)) return;
    const int r  = idx / (IW + 1);
    const int cc = idx - r * (IW + 1) - 1;
    const int oL = r * IW + cc;
    const bool okL = (cc >= 0);
    const bool okR = (cc + 1 < IW);
    uint4 e;
    #pragma unroll
    for (int b = 0; b < 4; ++b) {
        float l  = okL ? x[oL + b * IMG_STRIDE]     : 0.f;
        float rr = okR ? x[oL + 1 + b * IMG_STRIDE] : 0.f;
        __half2 h = __floats2half2_rn(l, rr);
        ((unsigned int*)&e)[b] = *(const unsigned int*)&h;
    }
    g_pair[(r + PAD) * PW + (cc + PAD)] = e;
}

// ---------------------------------------------------------------------------
__global__ void prep_fillT_kernel(const float* __restrict__ x) {
    int idx = blockIdx.x * blockDim.x + threadIdx.x;
    if (idx >= IW * (IW + 1)) return;
    const int rr = idx / IW - 1;
    const int c  = idx - (rr + 1) * IW;
    const int oT = rr * IW + c;
    const bool okT = (rr >= 0);
    const bool okB = (rr + 1 < IW);
    uint4 e;
    #pragma unroll
    for (int b = 0; b < 4; ++b) {
        float tv = okT ? x[oT + b * IMG_STRIDE]      : 0.f;
        float bv = okB ? x[oT + IW + b * IMG_STRIDE] : 0.f;
        __half2 h = __floats2half2_rn(tv, bv);
        ((unsigned int*)&e)[b] = *(const unsigned int*)&h;
    }
    g_pairT[(c + PAD) * PW + (rr + PAD)] = e;
}

// ---------------------------------------------------------------------------
// Radon for t in 0..89; column sums -> P_t, row sums -> P_{t+90} (mirrored).
// Row partials: 1-level fp16 pair exchange (2 SHFL + 1 STS-wf per iter).
// ---------------------------------------------------------------------------
__global__ __launch_bounds__(256, 6) void radon_kernel(const float* __restrict__ theta) {
    // s_row[warp][h][pairpos] : uint2 = (half2 batches01, half2 batches23)  (32KB)
    __shared__ uint2 s_row[8][HCH][4];

    const int t    = blockIdx.x;
    const int wt   = blockIdx.y;
    const int ch   = blockIdx.z;
    const int tid  = threadIdx.x;
    const int warp = tid >> 5;
    const int lane = tid & 31;
    const int wl   = lane & 7;
    const int hl   = lane >> 3;
    const int w    = wt * 64 + warp * 8 + wl;

    // zero row-partial slab (skipped k's must read as 0)
    {
        uint4* sr = (uint4*)&s_row[0][0][0];
        #pragma unroll
        for (int i = 0; i < 8; ++i)
            sr[tid + 256 * i] = make_uint4(0u, 0u, 0u, 0u);
    }
    __syncthreads();

    const float rad = theta[t] * 0.017453292519943295f;
    float s, c;
    sincosf(rad, &s, &c);

    float cA, sA, cB, sB;
    const uint4* __restrict__ img;
    if (fabsf(s) > fabsf(c)) { cA = -s; sA = c; cB = c;  sB = s; img = g_pairT; }
    else                     { cA = c;  sA = s; cB = -s; sB = c; img = g_pair;  }

    const float wf    = (float)w - 255.5f;
    const float colw  = fmaf(cA, wf, 383.5f);
    const float roww  = fmaf(cB, wf, 383.5f);
    const float hbase = (float)(ch * HCH) - 255.5f;

    // warp-uniform valid-k interval (nonzero bilinear support: coord in [127,640))
    const float wfa = (float)(wt * 64 + warp * 8) - 255.5f;
    const float wfb = wfa + 7.0f;
    float t1a = cB * wfa, t1b = cB * wfb;
    const float rA = 383.5f + fminf(t1a, t1b);
    const float rB = 383.5f + fmaxf(t1a, t1b) + 3.0f * sB;
    const float rh = sB * hbase;
    const float inv4sB = 1.0f / (4.0f * sB);
    float kL = (127.0f - rB - rh) * inv4sB;
    float kU = (641.0f - rA - rh) * inv4sB;
    float t2a = cA * wfa, t2b = cA * wfb;
    const float cC = 383.5f + fminf(t2a, t2b) + fminf(0.f, 3.f * sA);
    const float cD = 383.5f + fmaxf(t2a, t2b) + fmaxf(0.f, 3.f * sA);
    if (sA > 0.01f) {
        const float inv = 1.0f / (4.0f * sA);
        kL = fmaxf(kL, (127.0f - cD - sA * hbase) * inv);
        kU = fminf(kU, (641.0f - cC - sA * hbase) * inv);
    } else if (sA < -0.01f) {
        const float inv = 1.0f / (4.0f * sA);
        kL = fmaxf(kL, (641.0f - cC - sA * hbase) * inv);
        kU = fminf(kU, (127.0f - cD - sA * hbase) * inv);
    }
    const int k0 = max(0, (int)floorf(kL) - 1);
    const int k1 = min(HCH / 4, (int)floorf(kU) + 2);

    float acc0 = 0.f, acc1 = 0.f, acc2 = 0.f, acc3 = 0.f;
    const unsigned m = 0xFFFFFFFFu;

    if (k0 < k1) {
        float hf = hbase + (float)hl + 4.0f * (float)k0;

        float colv = fmaf(sA, hf, colw);
        float rowv = fmaf(sB, hf, roww);
        float cf = floorf(colv), rf = floorf(rowv);
        const uint4* p = img + ((int)rf * PW + (int)cf);
        uint4 qT = p[0];
        uint4 qB = p[PW];
        float fc = colv - cf, fr = rowv - rf;

        for (int k = k0; k < k1; ++k) {
            hf += 4.0f;
            const float colv2 = fmaf(sA, hf, colw);
            const float rowv2 = fmaf(sB, hf, roww);
            const float cf2 = floorf(colv2), rf2 = floorf(rowv2);
            const uint4* p2 = img + ((int)rf2 * PW + (int)cf2);
            const uint4 nT = p2[0], nB = p2[PW];

            const float gc = 1.f - fc, gr = 1.f - fr;
            const float w00 = gr * gc, w01 = gr * fc, w10 = fr * gc, w11 = fr * fc;
            const float2 t0 = __half22float2(*(const __half2*)&qT.x);
            const float2 t1 = __half22float2(*(const __half2*)&qT.y);
            const float2 t2 = __half22float2(*(const __half2*)&qT.z);
            const float2 t3 = __half22float2(*(const __half2*)&qT.w);
            const float2 b0 = __half22float2(*(const __half2*)&qB.x);
            const float2 b1 = __half22float2(*(const __half2*)&qB.y);
            const float2 b2 = __half22float2(*(const __half2*)&qB.z);
            const float2 b3 = __half22float2(*(const __half2*)&qB.w);

            float vx = fmaf(t0.x, w00, fmaf(t0.y, w01, fmaf(b0.x, w10, b0.y * w11)));
            float vy = fmaf(t1.x, w00, fmaf(t1.y, w01, fmaf(b1.x, w10, b1.y * w11)));
            float vz = fmaf(t2.x, w00, fmaf(t2.y, w01, fmaf(b2.x, w10, b2.y * w11)));
            float vw = fmaf(t3.x, w00, fmaf(t3.y, w01, fmaf(b3.x, w10, b3.y * w11)));

            // column accumulation (-> P_t), fp32
            acc0 += vx; acc1 += vy; acc2 += vz; acc3 += vw;

            // row partial: fp16 pack + 1-level exchange + pair store
            __half2 h01 = __floats2half2_rn(vx, vy);
            __half2 h23 = __floats2half2_rn(vz, vw);
            unsigned u01 = *(unsigned*)&h01;
            unsigned u23 = *(unsigned*)&h23;
            unsigned r01 = __shfl_xor_sync(m, u01, 1);
            unsigned r23 = __shfl_xor_sync(m, u23, 1);
            __half2 s01 = __hadd2(h01, *(__half2*)&r01);
            __half2 s23 = __hadd2(h23, *(__half2*)&r23);
            if ((wl & 1) == 0)
                s_row[warp][hl + 4 * k][wl >> 1] =
                    make_uint2(*(unsigned*)&s01, *(unsigned*)&s23);

            qT = nT; qB = nB;
            fc = colv2 - cf2;
            fr = rowv2 - rf2;
        }
    }

    // column partial: reduce 4 h-sublanes
    acc0 += __shfl_xor_sync(m, acc0, 8);  acc1 += __shfl_xor_sync(m, acc1, 8);
    acc2 += __shfl_xor_sync(m, acc2, 8);  acc3 += __shfl_xor_sync(m, acc3, 8);
    acc0 += __shfl_xor_sync(m, acc0, 16); acc1 += __shfl_xor_sync(m, acc1, 16);
    acc2 += __shfl_xor_sync(m, acc2, 16); acc3 += __shfl_xor_sync(m, acc3, 16);
    if (hl == 0) {
        g_colpart[0][ch][t][w] = acc0;
        g_colpart[1][ch][t][w] = acc1;
        g_colpart[2][ch][t][w] = acc2;
        g_colpart[3][ch][t][w] = acc3;
    }

    // row partial tail: sum 8 warps x 4 pairpos (fp16 pairs -> fp32)
    __syncthreads();
    if (tid < HCH) {
        float s0 = 0.f, s1 = 0.f, s2 = 0.f, s3 = 0.f;
        #pragma unroll
        for (int wp = 0; wp < 8; ++wp) {
            const uint4* rowp = (const uint4*)&s_row[wp][tid][0];
            #pragma unroll
            for (int q = 0; q < 2; ++q) {
                uint4 u = rowp[q];
                float2 a01 = __half22float2(*(const __half2*)&u.x);
                float2 a23 = __half22float2(*(const __half2*)&u.y);
                float2 c01 = __half22float2(*(const __half2*)&u.z);
                float2 c23 = __half22float2(*(const __half2*)&u.w);
                s0 += a01.x + c01.x; s1 += a01.y + c01.y;
                s2 += a23.x + c23.x; s3 += a23.y + c23.y;
            }
        }
        const int h = ch * HCH + tid;
        g_rowpart[0][t][wt][h] = s0;
        g_rowpart[1][t][wt][h] = s1;
        g_rowpart[2][t][wt][h] = s2;
        g_rowpart[3][t][wt][h] = s3;
    }
}

// ---------------------------------------------------------------------------
__global__ void reduce_kernel(float* __restrict__ out) {
    int idx = blockIdx.x * blockDim.x + threadIdx.x;   // [n][t][w], w fastest
    if (idx >= NB * NT * IW) return;
    const int w  = idx & (IW - 1);
    const int nt = idx >> 9;
    const int t  = nt % NT;
    const int n  = nt / NT;

    float sum = 0.f;
    if (t < NTH) {
        #pragma unroll
        for (int ch = 0; ch < NCH; ++ch)
            sum += g_colpart[n][ch][t][w];
    } else {
        const int th = t - NTH;
        const int h  = IW - 1 - w;
        #pragma unroll
        for (int wt = 0; wt < NWT; ++wt)
            sum += g_rowpart[n][th][wt][h];
    }
    out[n * (IW * NT) + w * NT + t] = sum;
}

// ---------------------------------------------------------------------------
extern "C" void kernel_launch(void* const* d_in, const int* in_sizes, int n_in,
                              void* d_out, int out_size) {
    const float* x  = (const float*)d_in[0];
    const float* th = (const float*)d_in[1];
    if (n_in >= 2 && in_sizes[0] == NT) {
        const float* tmp = x; x = th; th = tmp;
    }
    float* out = (float*)d_out;

    prep_border_kernel<<<(PW * PW + 255) / 256, 256>>>();
    prep_fill_kernel <<<(IW * (IW + 1) + 255) / 256, 256>>>(x);
    prep_fillT_kernel<<<(IW * (IW + 1) + 255) / 256, 256>>>(x);

    dim3 grid(NTH, NWT, NCH);
    radon_kernel<<<grid, 256>>>(th);

    reduce_kernel<<<(NB * NT * IW + 255) / 256, 256>>>(out);
}

// round 9
// speedup vs baseline: 2.4638x; 1.0006x over previous
#include <cuda_runtime.h>
#include <cuda_fp16.h>

#define IW   512
#define NB   4
#define NT   180
#define NTH  90             // sampled angles; 90..179 via row sums
#define PAD  128
#define PW   (IW + 2*PAD)   // 768
#define NCH  4
#define HCH  (IW / NCH)     // 128
#define NWT  8
#define IMG_STRIDE (IW*IW)

// Pair entry at (r,c): 4 x __half2 = 16B = (pix[r][c], pix[r][c+1]) per batch
__device__ uint4 g_pair [PW * PW];
__device__ uint4 g_pairT[PW * PW];
__device__ float g_colpart[NB][NCH][NTH][IW];
__device__ float g_rowpart[NB][NTH][NWT][IW];

// ---------------------------------------------------------------------------
__global__ void prep_border_kernel() {
    int idx = blockIdx.x * blockDim.x + threadIdx.x;
    if (idx >= PW * PW) return;
    int row = idx / PW;
    int col = idx - row * PW;
    if ((unsigned)(row - PAD) < (unsigned)IW &&
        (unsigned)(col - (PAD - 1)) < (unsigned)(IW + 1))
        return;
    const uint4 z = make_uint4(0u, 0u, 0u, 0u);
    g_pair [idx] = z;
    g_pairT[idx] = z;
}

// ---------------------------------------------------------------------------
__global__ void prep_fill_kernel(const float* __restrict__ x) {
    int idx = blockIdx.x * blockDim.x + threadIdx.x;
    if (idx >= IW * (IW + 1)) return;
    const int r  = idx / (IW + 1);
    const int cc = idx - r * (IW + 1) - 1;
    const int oL = r * IW + cc;
    const bool okL = (cc >= 0);
    const bool okR = (cc + 1 < IW);
    uint4 e;
    #pragma unroll
    for (int b = 0; b < 4; ++b) {
        float l  = okL ? x[oL + b * IMG_STRIDE]     : 0.f;
        float rr = okR ? x[oL + 1 + b * IMG_STRIDE] : 0.f;
        __half2 h = __floats2half2_rn(l, rr);
        ((unsigned int*)&e)[b] = *(const unsigned int*)&h;
    }
    g_pair[(r + PAD) * PW + (cc + PAD)] = e;
}

// ---------------------------------------------------------------------------
__global__ void prep_fillT_kernel(const float* __restrict__ x) {
    int idx = blockIdx.x * blockDim.x + threadIdx.x;
    if (idx >= IW * (IW + 1)) return;
    const int rr = idx / IW - 1;
    const int c  = idx - (rr + 1) * IW;
    const int oT = rr * IW + c;
    const bool okT = (rr >= 0);
    const bool okB = (rr + 1 < IW);
    uint4 e;
    #pragma unroll
    for (int b = 0; b < 4; ++b) {
        float tv = okT ? x[oT + b * IMG_STRIDE]      : 0.f;
        float bv = okB ? x[oT + IW + b * IMG_STRIDE] : 0.f;
        __half2 h = __floats2half2_rn(tv, bv);
        ((unsigned int*)&e)[b] = *(const unsigned int*)&h;
    }
    g_pairT[(c + PAD) * PW + (rr + PAD)] = e;
}

// ---------------------------------------------------------------------------
// Radon for t in 0..89; column sums -> P_t, row sums -> P_{t+90} (mirrored).
// ---------------------------------------------------------------------------
__global__ __launch_bounds__(256, 6) void radon_kernel(const float* __restrict__ theta) {
    // s_row[warp][h][pairpos] : uint2 = (half2 batches01, half2 batches23)  (32KB)
    __shared__ uint2 s_row[8][HCH][4];

    const int t    = blockIdx.x;
    const int wt   = blockIdx.y;
    const int ch   = blockIdx.z;
    const int tid  = threadIdx.x;
    const int warp = tid >> 5;
    const int lane = tid & 31;
    const int wl   = lane & 7;
    const int hl   = lane >> 3;
    const int w    = wt * 64 + warp * 8 + wl;

    // zero row-partial slab (skipped k's must read as 0)
    {
        uint4* sr = (uint4*)&s_row[0][0][0];
        #pragma unroll
        for (int i = 0; i < 8; ++i)
            sr[tid + 256 * i] = make_uint4(0u, 0u, 0u, 0u);
    }
    __syncthreads();

    const float rad = theta[t] * 0.017453292519943295f;
    float s, c;
    sincosf(rad, &s, &c);

    float cA, sA, cB, sB;
    const uint4* __restrict__ img;
    if (fabsf(s) > fabsf(c)) { cA = -s; sA = c; cB = c;  sB = s; img = g_pairT; }
    else                     { cA = c;  sA = s; cB = -s; sB = c; img = g_pair;  }

    const float wf    = (float)w - 255.5f;
    const float colw  = fmaf(cA, wf, 383.5f);
    const float roww  = fmaf(cB, wf, 383.5f);
    const float hbase = (float)(ch * HCH) - 255.5f;

    // warp-uniform valid-k interval (nonzero bilinear support: coord in [127,640))
    const float wfa = (float)(wt * 64 + warp * 8) - 255.5f;
    const float wfb = wfa + 7.0f;
    float t1a = cB * wfa, t1b = cB * wfb;
    const float rA = 383.5f + fminf(t1a, t1b);
    const float rB = 383.5f + fmaxf(t1a, t1b) + 3.0f * sB;
    const float rh = sB * hbase;
    const float inv4sB = 1.0f / (4.0f * sB);
    float kL = (127.0f - rB - rh) * inv4sB;
    float kU = (640.0f - rA - rh) * inv4sB;
    float t2a = cA * wfa, t2b = cA * wfb;
    const float cC = 383.5f + fminf(t2a, t2b) + fminf(0.f, 3.f * sA);
    const float cD = 383.5f + fmaxf(t2a, t2b) + fmaxf(0.f, 3.f * sA);
    if (sA > 0.01f) {
        const float inv = 1.0f / (4.0f * sA);
        kL = fmaxf(kL, (127.0f - cD - sA * hbase) * inv);
        kU = fminf(kU, (640.0f - cC - sA * hbase) * inv);
    } else if (sA < -0.01f) {
        const float inv = 1.0f / (4.0f * sA);
        kL = fmaxf(kL, (640.0f - cC - sA * hbase) * inv);
        kU = fminf(kU, (127.0f - cD - sA * hbase) * inv);
    }
    // exact-ish bounds with 1 full iteration of fp slack on each side
    const int k0 = max(0, (int)floorf(kL));
    const int k1 = min(HCH / 4, (int)floorf(kU) + 1);

    float acc0 = 0.f, acc1 = 0.f, acc2 = 0.f, acc3 = 0.f;
    const unsigned m = 0xFFFFFFFFu;

    if (k0 < k1) {
        float hf = hbase + (float)hl + 4.0f * (float)k0;

        float colv = fmaf(sA, hf, colw);
        float rowv = fmaf(sB, hf, roww);
        float cf = floorf(colv), rf = floorf(rowv);
        const uint4* p = img + (int)fmaf(rf, (float)PW, cf);
        uint4 qT = p[0];
        uint4 qB = p[PW];
        float fc = colv - cf, fr = rowv - rf;

        #pragma unroll 2
        for (int k = k0; k < k1; ++k) {
            hf += 4.0f;
            const float colv2 = fmaf(sA, hf, colw);
            const float rowv2 = fmaf(sB, hf, roww);
            const float cf2 = floorf(colv2), rf2 = floorf(rowv2);
            const uint4* p2 = img + (int)fmaf(rf2, (float)PW, cf2);
            const uint4 nT = p2[0], nB = p2[PW];

            const float gc = 1.f - fc, gr = 1.f - fr;
            const float w00 = gr * gc, w01 = gr * fc, w10 = fr * gc, w11 = fr * fc;
            const float2 t0 = __half22float2(*(const __half2*)&qT.x);
            const float2 t1 = __half22float2(*(const __half2*)&qT.y);
            const float2 t2 = __half22float2(*(const __half2*)&qT.z);
            const float2 t3 = __half22float2(*(const __half2*)&qT.w);
            const float2 b0 = __half22float2(*(const __half2*)&qB.x);
            const float2 b1 = __half22float2(*(const __half2*)&qB.y);
            const float2 b2 = __half22float2(*(const __half2*)&qB.z);
            const float2 b3 = __half22float2(*(const __half2*)&qB.w);

            float vx = fmaf(t0.x, w00, fmaf(t0.y, w01, fmaf(b0.x, w10, b0.y * w11)));
            float vy = fmaf(t1.x, w00, fmaf(t1.y, w01, fmaf(b1.x, w10, b1.y * w11)));
            float vz = fmaf(t2.x, w00, fmaf(t2.y, w01, fmaf(b2.x, w10, b2.y * w11)));
            float vw = fmaf(t3.x, w00, fmaf(t3.y, w01, fmaf(b3.x, w10, b3.y * w11)));

            // column accumulation (-> P_t), fp32
            acc0 += vx; acc1 += vy; acc2 += vz; acc3 += vw;

            // row partial: fp16 pack + 1-level exchange + pair store
            __half2 h01 = __floats2half2_rn(vx, vy);
            __half2 h23 = __floats2half2_rn(vz, vw);
            unsigned u01 = *(unsigned*)&h01;
            unsigned u23 = *(unsigned*)&h23;
            unsigned r01 = __shfl_xor_sync(m, u01, 1);
            unsigned r23 = __shfl_xor_sync(m, u23, 1);
            __half2 s01 = __hadd2(h01, *(__half2*)&r01);
            __half2 s23 = __hadd2(h23, *(__half2*)&r23);
            if ((wl & 1) == 0)
                s_row[warp][hl + 4 * k][wl >> 1] =
                    make_uint2(*(unsigned*)&s01, *(unsigned*)&s23);

            qT = nT; qB = nB;
            fc = colv2 - cf2;
            fr = rowv2 - rf2;
        }
    }

    // column partial: reduce 4 h-sublanes
    acc0 += __shfl_xor_sync(m, acc0, 8);  acc1 += __shfl_xor_sync(m, acc1, 8);
    acc2 += __shfl_xor_sync(m, acc2, 8);  acc3 += __shfl_xor_sync(m, acc3, 8);
    acc0 += __shfl_xor_sync(m, acc0, 16); acc1 += __shfl_xor_sync(m, acc1, 16);
    acc2 += __shfl_xor_sync(m, acc2, 16); acc3 += __shfl_xor_sync(m, acc3, 16);
    if (hl == 0) {
        g_colpart[0][ch][t][w] = acc0;
        g_colpart[1][ch][t][w] = acc1;
        g_colpart[2][ch][t][w] = acc2;
        g_colpart[3][ch][t][w] = acc3;
    }

    // row partial tail: sum 8 warps x 4 pairpos (fp16 pairs -> fp32)
    __syncthreads();
    if (tid < HCH) {
        float s0 = 0.f, s1 = 0.f, s2 = 0.f, s3 = 0.f;
        #pragma unroll
        for (int wp = 0; wp < 8; ++wp) {
            const uint4* rowp = (const uint4*)&s_row[wp][tid][0];
            #pragma unroll
            for (int q = 0; q < 2; ++q) {
                uint4 u = rowp[q];
                float2 a01 = __half22float2(*(const __half2*)&u.x);
                float2 a23 = __half22float2(*(const __half2*)&u.y);
                float2 c01 = __half22float2(*(const __half2*)&u.z);
                float2 c23 = __half22float2(*(const __half2*)&u.w);
                s0 += a01.x + c01.x; s1 += a01.y + c01.y;
                s2 += a23.x + c23.x; s3 += a23.y + c23.y;
            }
        }
        const int h = ch * HCH + tid;
        g_rowpart[0][t][wt][h] = s0;
        g_rowpart[1][t][wt][h] = s1;
        g_rowpart[2][t][wt][h] = s2;
        g_rowpart[3][t][wt][h] = s3;
    }
}

// ---------------------------------------------------------------------------
__global__ void reduce_kernel(float* __restrict__ out) {
    int idx = blockIdx.x * blockDim.x + threadIdx.x;   // [n][t][w], w fastest
    if (idx >= NB * NT * IW) return;
    const int w  = idx & (IW - 1);
    const int nt = idx >> 9;
    const int t  = nt % NT;
    const int n  = nt / NT;

    float sum = 0.f;
    if (t < NTH) {
        #pragma unroll
        for (int ch = 0; ch < NCH; ++ch)
            sum += g_colpart[n][ch][t][w];
    } else {
        const int th = t - NTH;
        const int h  = IW - 1 - w;
        #pragma unroll
        for (int wt = 0; wt < NWT; ++wt)
            sum += g_rowpart[n][th][wt][h];
    }
    out[n * (IW * NT) + w * NT + t] = sum;
}

// ---------------------------------------------------------------------------
extern "C" void kernel_launch(void* const* d_in, const int* in_sizes, int n_in,
                              void* d_out, int out_size) {
    const float* x  = (const float*)d_in[0];
    const float* th = (const float*)d_in[1];
    if (n_in >= 2 && in_sizes[0] == NT) {
        const float* tmp = x; x = th; th = tmp;
    }
    float* out = (float*)d_out;

    prep_border_kernel<<<(PW * PW + 255) / 256, 256>>>();
    prep_fill_kernel <<<(IW * (IW + 1) + 255) / 256, 256>>>(x);
    prep_fillT_kernel<<<(IW * (IW + 1) + 255) / 256, 256>>>(x);

    dim3 grid(NTH, NWT, NCH);
    radon_kernel<<<grid, 256>>>(th);

    reduce_kernel<<<(NB * NT * IW + 255) / 256, 256>>>(out);
}

// round 10
// speedup vs baseline: 2.6158x; 1.0617x over previous
#include <cuda_runtime.h>
#include <cuda_fp16.h>

#define IW   512
#define NB   4
#define NT   180
#define NTH  90             // sampled angles; 90..179 via row sums
#define PAD  128
#define PW   (IW + 2*PAD)   // 768
#define NCH  4
#define HCH  (IW / NCH)     // 128
#define NWT  8
#define IMG_STRIDE (IW*IW)

// 32B entry at (r,c): full 2x2 bilinear stencil x 4 batches, fp16.
//  t = top row:    batch b -> half2(pix[r][c],   pix[r][c+1])
//  b = bottom row: batch b -> half2(pix[r+1][c], pix[r+1][c+1])
struct __align__(32) E32 { uint4 t, b; };

__device__ E32  g_pair [PW * PW];                  // 18.9 MB
__device__ E32  g_pairT[PW * PW];                  // 18.9 MB
__device__ float g_colpart[NB][NCH][NTH][IW];
__device__ float g_rowpart[NB][NTH][NWT][IW];

// 256-bit global load (sm_100+)
__device__ __forceinline__ void ldg256(const E32* p, uint4& t, uint4& b) {
    asm("ld.global.v8.b32 {%0,%1,%2,%3,%4,%5,%6,%7}, [%8];"
        : "=r"(t.x), "=r"(t.y), "=r"(t.z), "=r"(t.w),
          "=r"(b.x), "=r"(b.y), "=r"(b.z), "=r"(b.w)
        : "l"(p));
}

// ---------------------------------------------------------------------------
// Zero everything outside the filled rect rows/cols [PAD-1, PAD+IW)
// ---------------------------------------------------------------------------
__global__ void prep_border_kernel() {
    int idx = blockIdx.x * blockDim.x + threadIdx.x;
    if (idx >= PW * PW) return;
    int row = idx / PW;
    int col = idx - row * PW;
    if ((unsigned)(row - (PAD - 1)) < (unsigned)(IW + 1) &&
        (unsigned)(col - (PAD - 1)) < (unsigned)(IW + 1))
        return;
    const uint4 z = make_uint4(0u, 0u, 0u, 0u);
    g_pair [idx].t = z; g_pair [idx].b = z;
    g_pairT[idx].t = z; g_pairT[idx].b = z;
}

// ---------------------------------------------------------------------------
// Fill both orientations from shared pixel reads. (r,c) in [-1, IW)^2.
// normal entry(r,c):  top=(r,c),(r,c+1)    bottom=(r+1,c),(r+1,c+1)
// transposed entry at (R=c, C=r): top=(r,c),(r+1,c)  bottom=(r,c+1),(r+1,c+1)
// ---------------------------------------------------------------------------
__global__ void prep_fill_kernel(const float* __restrict__ x) {
    int idx = blockIdx.x * blockDim.x + threadIdx.x;
    if (idx >= (IW + 1) * (IW + 1)) return;
    const int r = idx / (IW + 1) - 1;
    const int c = idx - (r + 1) * (IW + 1) - 1;

    const bool r0 = (unsigned)r < (unsigned)IW;
    const bool r1 = (unsigned)(r + 1) < (unsigned)IW;
    const bool c0 = (unsigned)c < (unsigned)IW;
    const bool c1 = (unsigned)(c + 1) < (unsigned)IW;
    const int base = r * IW + c;

    E32 en, et;
    #pragma unroll
    for (int bb = 0; bb < 4; ++bb) {
        const float* xb = x + bb * IMG_STRIDE;
        float p00 = (r0 && c0) ? xb[base]          : 0.f;
        float p01 = (r0 && c1) ? xb[base + 1]      : 0.f;
        float p10 = (r1 && c0) ? xb[base + IW]     : 0.f;
        float p11 = (r1 && c1) ? xb[base + IW + 1] : 0.f;
        __half2 nt = __floats2half2_rn(p00, p01);
        __half2 nb = __floats2half2_rn(p10, p11);
        __half2 tt = __floats2half2_rn(p00, p10);
        __half2 tb = __floats2half2_rn(p01, p11);
        ((unsigned*)&en.t)[bb] = *(unsigned*)&nt;
        ((unsigned*)&en.b)[bb] = *(unsigned*)&nb;
        ((unsigned*)&et.t)[bb] = *(unsigned*)&tt;
        ((unsigned*)&et.b)[bb] = *(unsigned*)&tb;
    }
    g_pair [(r + PAD) * PW + (c + PAD)] = en;
    g_pairT[(c + PAD) * PW + (r + PAD)] = et;
}

// ---------------------------------------------------------------------------
// Radon for t in 0..89; column sums -> P_t, row sums -> P_{t+90} (mirrored).
// One 256-bit load per bilinear sample.
// ---------------------------------------------------------------------------
__global__ __launch_bounds__(256, 6) void radon_kernel(const float* __restrict__ theta) {
    // s_row[warp][h][pairpos] : uint2 = (half2 batches01, half2 batches23)  (32KB)
    __shared__ uint2 s_row[8][HCH][4];

    const int t    = blockIdx.x;
    const int wt   = blockIdx.y;
    const int ch   = blockIdx.z;
    const int tid  = threadIdx.x;
    const int warp = tid >> 5;
    const int lane = tid & 31;
    const int wl   = lane & 7;
    const int hl   = lane >> 3;
    const int w    = wt * 64 + warp * 8 + wl;

    // zero row-partial slab (skipped k's must read as 0)
    {
        uint4* sr = (uint4*)&s_row[0][0][0];
        #pragma unroll
        for (int i = 0; i < 8; ++i)
            sr[tid + 256 * i] = make_uint4(0u, 0u, 0u, 0u);
    }
    __syncthreads();

    const float rad = theta[t] * 0.017453292519943295f;
    float s, c;
    sincosf(rad, &s, &c);

    float cA, sA, cB, sB;
    const E32* __restrict__ img;
    if (fabsf(s) > fabsf(c)) { cA = -s; sA = c; cB = c;  sB = s; img = g_pairT; }
    else                     { cA = c;  sA = s; cB = -s; sB = c; img = g_pair;  }

    const float wf    = (float)w - 255.5f;
    const float colw  = fmaf(cA, wf, 383.5f);
    const float roww  = fmaf(cB, wf, 383.5f);
    const float hbase = (float)(ch * HCH) - 255.5f;

    // warp-uniform valid-k interval (nonzero bilinear support: coord in [127,640))
    const float wfa = (float)(wt * 64 + warp * 8) - 255.5f;
    const float wfb = wfa + 7.0f;
    float t1a = cB * wfa, t1b = cB * wfb;
    const float rA = 383.5f + fminf(t1a, t1b);
    const float rB = 383.5f + fmaxf(t1a, t1b) + 3.0f * sB;
    const float rh = sB * hbase;
    const float inv4sB = 1.0f / (4.0f * sB);
    float kL = (127.0f - rB - rh) * inv4sB;
    float kU = (640.0f - rA - rh) * inv4sB;
    float t2a = cA * wfa, t2b = cA * wfb;
    const float cC = 383.5f + fminf(t2a, t2b) + fminf(0.f, 3.f * sA);
    const float cD = 383.5f + fmaxf(t2a, t2b) + fmaxf(0.f, 3.f * sA);
    if (sA > 0.01f) {
        const float inv = 1.0f / (4.0f * sA);
        kL = fmaxf(kL, (127.0f - cD - sA * hbase) * inv);
        kU = fminf(kU, (640.0f - cC - sA * hbase) * inv);
    } else if (sA < -0.01f) {
        const float inv = 1.0f / (4.0f * sA);
        kL = fmaxf(kL, (640.0f - cC - sA * hbase) * inv);
        kU = fminf(kU, (127.0f - cD - sA * hbase) * inv);
    }
    const int k0 = max(0, (int)floorf(kL));
    const int k1 = min(HCH / 4, (int)floorf(kU) + 1);

    float acc0 = 0.f, acc1 = 0.f, acc2 = 0.f, acc3 = 0.f;
    const unsigned m = 0xFFFFFFFFu;

    if (k0 < k1) {
        float hf = hbase + (float)hl + 4.0f * (float)k0;

        float colv = fmaf(sA, hf, colw);
        float rowv = fmaf(sB, hf, roww);
        float cf = floorf(colv), rf = floorf(rowv);
        uint4 qT, qB;
        ldg256(img + (int)fmaf(rf, (float)PW, cf), qT, qB);
        float fc = colv - cf, fr = rowv - rf;

        for (int k = k0; k < k1; ++k) {
            // prefetch next iteration (always in-bounds: PAD=128)
            hf += 4.0f;
            const float colv2 = fmaf(sA, hf, colw);
            const float rowv2 = fmaf(sB, hf, roww);
            const float cf2 = floorf(colv2), rf2 = floorf(rowv2);
            uint4 nT, nB;
            ldg256(img + (int)fmaf(rf2, (float)PW, cf2), nT, nB);

            const float gc = 1.f - fc, gr = 1.f - fr;
            const float w00 = gr * gc, w01 = gr * fc, w10 = fr * gc, w11 = fr * fc;
            const float2 t0 = __half22float2(*(const __half2*)&qT.x);
            const float2 t1 = __half22float2(*(const __half2*)&qT.y);
            const float2 t2 = __half22float2(*(const __half2*)&qT.z);
            const float2 t3 = __half22float2(*(const __half2*)&qT.w);
            const float2 b0 = __half22float2(*(const __half2*)&qB.x);
            const float2 b1 = __half22float2(*(const __half2*)&qB.y);
            const float2 b2 = __half22float2(*(const __half2*)&qB.z);
            const float2 b3 = __half22float2(*(const __half2*)&qB.w);

            float vx = fmaf(t0.x, w00, fmaf(t0.y, w01, fmaf(b0.x, w10, b0.y * w11)));
            float vy = fmaf(t1.x, w00, fmaf(t1.y, w01, fmaf(b1.x, w10, b1.y * w11)));
            float vz = fmaf(t2.x, w00, fmaf(t2.y, w01, fmaf(b2.x, w10, b2.y * w11)));
            float vw = fmaf(t3.x, w00, fmaf(t3.y, w01, fmaf(b3.x, w10, b3.y * w11)));

            // column accumulation (-> P_t), fp32
            acc0 += vx; acc1 += vy; acc2 += vz; acc3 += vw;

            // row partial: fp16 pack + 1-level exchange + pair store
            __half2 h01 = __floats2half2_rn(vx, vy);
            __half2 h23 = __floats2half2_rn(vz, vw);
            unsigned u01 = *(unsigned*)&h01;
            unsigned u23 = *(unsigned*)&h23;
            unsigned r01 = __shfl_xor_sync(m, u01, 1);
            unsigned r23 = __shfl_xor_sync(m, u23, 1);
            __half2 s01 = __hadd2(h01, *(__half2*)&r01);
            __half2 s23 = __hadd2(h23, *(__half2*)&r23);
            if ((wl & 1) == 0)
                s_row[warp][hl + 4 * k][wl >> 1] =
                    make_uint2(*(unsigned*)&s01, *(unsigned*)&s23);

            qT = nT; qB = nB;
            fc = colv2 - cf2;
            fr = rowv2 - rf2;
        }
    }

    // column partial: reduce 4 h-sublanes
    acc0 += __shfl_xor_sync(m, acc0, 8);  acc1 += __shfl_xor_sync(m, acc1, 8);
    acc2 += __shfl_xor_sync(m, acc2, 8);  acc3 += __shfl_xor_sync(m, acc3, 8);
    acc0 += __shfl_xor_sync(m, acc0, 16); acc1 += __shfl_xor_sync(m, acc1, 16);
    acc2 += __shfl_xor_sync(m, acc2, 16); acc3 += __shfl_xor_sync(m, acc3, 16);
    if (hl == 0) {
        g_colpart[0][ch][t][w] = acc0;
        g_colpart[1][ch][t][w] = acc1;
        g_colpart[2][ch][t][w] = acc2;
        g_colpart[3][ch][t][w] = acc3;
    }

    // row partial tail: sum 8 warps x 4 pairpos (fp16 pairs -> fp32)
    __syncthreads();
    if (tid < HCH) {
        float s0 = 0.f, s1 = 0.f, s2 = 0.f, s3 = 0.f;
        #pragma unroll
        for (int wp = 0; wp < 8; ++wp) {
            const uint4* rowp = (const uint4*)&s_row[wp][tid][0];
            #pragma unroll
            for (int q = 0; q < 2; ++q) {
                uint4 u = rowp[q];
                float2 a01 = __half22float2(*(const __half2*)&u.x);
                float2 a23 = __half22float2(*(const __half2*)&u.y);
                float2 c01 = __half22float2(*(const __half2*)&u.z);
                float2 c23 = __half22float2(*(const __half2*)&u.w);
                s0 += a01.x + c01.x; s1 += a01.y + c01.y;
                s2 += a23.x + c23.x; s3 += a23.y + c23.y;
            }
        }
        const int h = ch * HCH + tid;
        g_rowpart[0][t][wt][h] = s0;
        g_rowpart[1][t][wt][h] = s1;
        g_rowpart[2][t][wt][h] = s2;
        g_rowpart[3][t][wt][h] = s3;
    }
}

// ---------------------------------------------------------------------------
__global__ void reduce_kernel(float* __restrict__ out) {
    int idx = blockIdx.x * blockDim.x + threadIdx.x;   // [n][t][w], w fastest
    if (idx >= NB * NT * IW) return;
    const int w  = idx & (IW - 1);
    const int nt = idx >> 9;
    const int t  = nt % NT;
    const int n  = nt / NT;

    float sum = 0.f;
    if (t < NTH) {
        #pragma unroll
        for (int ch = 0; ch < NCH; ++ch)
            sum += g_colpart[n][ch][t][w];
    } else {
        const int th = t - NTH;
        const int h  = IW - 1 - w;
        #pragma unroll
        for (int wt = 0; wt < NWT; ++wt)
            sum += g_rowpart[n][th][wt][h];
    }
    out[n * (IW * NT) + w * NT + t] = sum;
}

// ---------------------------------------------------------------------------
extern "C" void kernel_launch(void* const* d_in, const int* in_sizes, int n_in,
                              void* d_out, int out_size) {
    const float* x  = (const float*)d_in[0];
    const float* th = (const float*)d_in[1];
    if (n_in >= 2 && in_sizes[0] == NT) {
        const float* tmp = x; x = th; th = tmp;
    }
    float* out = (float*)d_out;

    prep_border_kernel<<<(PW * PW + 255) / 256, 256>>>();
    prep_fill_kernel<<<((IW + 1) * (IW + 1) + 255) / 256, 256>>>(x);

    dim3 grid(NTH, NWT, NCH);
    radon_kernel<<<grid, 256>>>(th);

    reduce_kernel<<<(NB * NT * IW + 255) / 256, 256>>>(out);
}

// round 11
// speedup vs baseline: 2.6789x; 1.0241x over previous
#include <cuda_runtime.h>
#include <cuda_fp16.h>

#define IW   512
#define NB   4
#define NT   180
#define NTH  90             // sampled angles; 90..179 via row sums
#define PAD  16
#define PW   (IW + 2*PAD)   // 544
#define NCH  4
#define HCH  (IW / NCH)     // 128
#define NWT  8
#define IMG_STRIDE (IW*IW)
#define OFS  ((float)PAD + 255.5f)     // 271.5: padded-center offset
#define LO   ((float)PAD - 1.0f)       // nonzero support lower edge (15)
#define HI   ((float)PAD + 512.0f)     // nonzero support upper edge (528)

// 32B entry at (r,c): full 2x2 bilinear stencil x 4 batches, fp16.
struct __align__(32) E32 { uint4 t, b; };

__device__ E32  g_pair [PW * PW];                  // 9.5 MB
__device__ E32  g_pairT[PW * PW];                  // 9.5 MB
__device__ float g_colpart[NB][NCH][NTH][IW];      // fp32
__device__ uint2 g_rowpart[NTH][NWT][IW];          // half4 per (t,wt,h)

// 256-bit global load (sm_100+)
__device__ __forceinline__ void ldg256(const E32* p, uint4& t, uint4& b) {
    asm("ld.global.v8.b32 {%0,%1,%2,%3,%4,%5,%6,%7}, [%8];"
        : "=r"(t.x), "=r"(t.y), "=r"(t.z), "=r"(t.w),
          "=r"(b.x), "=r"(b.y), "=r"(b.z), "=r"(b.w)
        : "l"(p));
}

// ---------------------------------------------------------------------------
// Zero everything outside the filled rect rows/cols [PAD-1, PAD+IW)
// ---------------------------------------------------------------------------
__global__ void prep_border_kernel() {
    int idx = blockIdx.x * blockDim.x + threadIdx.x;
    if (idx >= PW * PW) return;
    int row = idx / PW;
    int col = idx - row * PW;
    if ((unsigned)(row - (PAD - 1)) < (unsigned)(IW + 1) &&
        (unsigned)(col - (PAD - 1)) < (unsigned)(IW + 1))
        return;
    const uint4 z = make_uint4(0u, 0u, 0u, 0u);
    g_pair [idx].t = z; g_pair [idx].b = z;
    g_pairT[idx].t = z; g_pairT[idx].b = z;
}

// ---------------------------------------------------------------------------
// Fill both orientations. (r,c) in [-1, IW)^2.
// normal entry(r,c):  top=(r,c),(r,c+1)    bottom=(r+1,c),(r+1,c+1)
// transposed entry at (R=c, C=r): top=(r,c),(r+1,c)  bottom=(r,c+1),(r+1,c+1)
// ---------------------------------------------------------------------------
__global__ void prep_fill_kernel(const float* __restrict__ x) {
    int idx = blockIdx.x * blockDim.x + threadIdx.x;
    if (idx >= (IW + 1) * (IW + 1)) return;
    const int r = idx / (IW + 1) - 1;
    const int c = idx - (r + 1) * (IW + 1) - 1;

    const bool r0 = (unsigned)r < (unsigned)IW;
    const bool r1 = (unsigned)(r + 1) < (unsigned)IW;
    const bool c0 = (unsigned)c < (unsigned)IW;
    const bool c1 = (unsigned)(c + 1) < (unsigned)IW;
    const int base = r * IW + c;

    E32 en, et;
    #pragma unroll
    for (int bb = 0; bb < 4; ++bb) {
        const float* xb = x + bb * IMG_STRIDE;
        float p00 = (r0 && c0) ? xb[base]          : 0.f;
        float p01 = (r0 && c1) ? xb[base + 1]      : 0.f;
        float p10 = (r1 && c0) ? xb[base + IW]     : 0.f;
        float p11 = (r1 && c1) ? xb[base + IW + 1] : 0.f;
        __half2 nt = __floats2half2_rn(p00, p01);
        __half2 nb = __floats2half2_rn(p10, p11);
        __half2 tt = __floats2half2_rn(p00, p10);
        __half2 tb = __floats2half2_rn(p01, p11);
        ((unsigned*)&en.t)[bb] = *(unsigned*)&nt;
        ((unsigned*)&en.b)[bb] = *(unsigned*)&nb;
        ((unsigned*)&et.t)[bb] = *(unsigned*)&tt;
        ((unsigned*)&et.b)[bb] = *(unsigned*)&tb;
    }
    g_pair [(r + PAD) * PW + (c + PAD)] = en;
    g_pairT[(c + PAD) * PW + (r + PAD)] = et;
}

// ---------------------------------------------------------------------------
// Radon for t in 0..89; column sums -> P_t, row sums -> P_{t+90} (mirrored).
// ---------------------------------------------------------------------------
__global__ __launch_bounds__(256, 6) void radon_kernel(const float* __restrict__ theta) {
    // s_row[warp][h][pairpos] : uint2 = (half2 batches01, half2 batches23)  (32KB)
    __shared__ uint2 s_row[8][HCH][4];

    const int t    = blockIdx.x;
    const int wt   = blockIdx.y;
    const int ch   = blockIdx.z;
    const int tid  = threadIdx.x;
    const int warp = tid >> 5;
    const int lane = tid & 31;
    const int wl   = lane & 7;
    const int hl   = lane >> 3;
    const int w    = wt * 64 + warp * 8 + wl;

    // zero row-partial slab (skipped k's must read as 0)
    {
        uint4* sr = (uint4*)&s_row[0][0][0];
        #pragma unroll
        for (int i = 0; i < 8; ++i)
            sr[tid + 256 * i] = make_uint4(0u, 0u, 0u, 0u);
    }
    __syncthreads();

    const float rad = theta[t] * 0.017453292519943295f;
    float s, c;
    sincosf(rad, &s, &c);

    float cA, sA, cB, sB;
    const E32* __restrict__ img;
    if (fabsf(s) > fabsf(c)) { cA = -s; sA = c; cB = c;  sB = s; img = g_pairT; }
    else                     { cA = c;  sA = s; cB = -s; sB = c; img = g_pair;  }

    const float wf    = (float)w - 255.5f;
    const float colw  = fmaf(cA, wf, OFS);
    const float roww  = fmaf(cB, wf, OFS);
    const float hbase = (float)(ch * HCH) - 255.5f;

    // warp-uniform valid-k interval (nonzero bilinear support: coord in (LO, HI))
    const float wfa = (float)(wt * 64 + warp * 8) - 255.5f;
    const float wfb = wfa + 7.0f;
    float t1a = cB * wfa, t1b = cB * wfb;
    const float rA = OFS + fminf(t1a, t1b);
    const float rB = OFS + fmaxf(t1a, t1b) + 3.0f * sB;
    const float rh = sB * hbase;
    const float inv4sB = 1.0f / (4.0f * sB);
    float kL = (LO - rB - rh) * inv4sB;
    float kU = (HI - rA - rh) * inv4sB;
    float t2a = cA * wfa, t2b = cA * wfb;
    const float cC = OFS + fminf(t2a, t2b) + fminf(0.f, 3.f * sA);
    const float cD = OFS + fmaxf(t2a, t2b) + fmaxf(0.f, 3.f * sA);
    if (sA > 0.01f) {
        const float inv = 1.0f / (4.0f * sA);
        kL = fmaxf(kL, (LO - cD - sA * hbase) * inv);
        kU = fminf(kU, (HI - cC - sA * hbase) * inv);
    } else if (sA < -0.01f) {
        const float inv = 1.0f / (4.0f * sA);
        kL = fmaxf(kL, (HI - cC - sA * hbase) * inv);
        kU = fminf(kU, (LO - cD - sA * hbase) * inv);
    }
    const int k0 = max(0, (int)floorf(kL));
    const int k1 = min(HCH / 4, (int)floorf(kU) + 1);

    float acc0 = 0.f, acc1 = 0.f, acc2 = 0.f, acc3 = 0.f;
    const unsigned m = 0xFFFFFFFFu;

    if (k0 < k1) {
        float hf = hbase + (float)hl + 4.0f * (float)k0;

        float colv = fmaf(sA, hf, colw);
        float rowv = fmaf(sB, hf, roww);
        float cf = floorf(colv), rf = floorf(rowv);
        uint4 qT, qB;
        ldg256(img + (int)fmaf(rf, (float)PW, cf), qT, qB);
        float fc = colv - cf, fr = rowv - rf;

        for (int k = k0; k < k1; ++k) {
            // prefetch next iteration (in-bounds: clamp margins cover k1)
            hf += 4.0f;
            const float colv2 = fmaf(sA, hf, colw);
            const float rowv2 = fmaf(sB, hf, roww);
            const float cf2 = floorf(colv2), rf2 = floorf(rowv2);
            uint4 nT, nB;
            ldg256(img + (int)fmaf(rf2, (float)PW, cf2), nT, nB);

            const float gc = 1.f - fc, gr = 1.f - fr;
            const float w00 = gr * gc, w01 = gr * fc, w10 = fr * gc, w11 = fr * fc;
            const float2 t0 = __half22float2(*(const __half2*)&qT.x);
            const float2 t1 = __half22float2(*(const __half2*)&qT.y);
            const float2 t2 = __half22float2(*(const __half2*)&qT.z);
            const float2 t3 = __half22float2(*(const __half2*)&qT.w);
            const float2 b0 = __half22float2(*(const __half2*)&qB.x);
            const float2 b1 = __half22float2(*(const __half2*)&qB.y);
            const float2 b2 = __half22float2(*(const __half2*)&qB.z);
            const float2 b3 = __half22float2(*(const __half2*)&qB.w);

            float vx = fmaf(t0.x, w00, fmaf(t0.y, w01, fmaf(b0.x, w10, b0.y * w11)));
            float vy = fmaf(t1.x, w00, fmaf(t1.y, w01, fmaf(b1.x, w10, b1.y * w11)));
            float vz = fmaf(t2.x, w00, fmaf(t2.y, w01, fmaf(b2.x, w10, b2.y * w11)));
            float vw = fmaf(t3.x, w00, fmaf(t3.y, w01, fmaf(b3.x, w10, b3.y * w11)));

            acc0 += vx; acc1 += vy; acc2 += vz; acc3 += vw;

            // row partial: fp16 pack + 1-level exchange + pair store
            __half2 h01 = __floats2half2_rn(vx, vy);
            __half2 h23 = __floats2half2_rn(vz, vw);
            unsigned u01 = *(unsigned*)&h01;
            unsigned u23 = *(unsigned*)&h23;
            unsigned r01 = __shfl_xor_sync(m, u01, 1);
            unsigned r23 = __shfl_xor_sync(m, u23, 1);
            __half2 s01 = __hadd2(h01, *(__half2*)&r01);
            __half2 s23 = __hadd2(h23, *(__half2*)&r23);
            if ((wl & 1) == 0)
                s_row[warp][hl + 4 * k][wl >> 1] =
                    make_uint2(*(unsigned*)&s01, *(unsigned*)&s23);

            qT = nT; qB = nB;
            fc = colv2 - cf2;
            fr = rowv2 - rf2;
        }
    }

    // column partial: reduce 4 h-sublanes
    acc0 += __shfl_xor_sync(m, acc0, 8);  acc1 += __shfl_xor_sync(m, acc1, 8);
    acc2 += __shfl_xor_sync(m, acc2, 8);  acc3 += __shfl_xor_sync(m, acc3, 8);
    acc0 += __shfl_xor_sync(m, acc0, 16); acc1 += __shfl_xor_sync(m, acc1, 16);
    acc2 += __shfl_xor_sync(m, acc2, 16); acc3 += __shfl_xor_sync(m, acc3, 16);
    if (hl == 0) {
        g_colpart[0][ch][t][w] = acc0;
        g_colpart[1][ch][t][w] = acc1;
        g_colpart[2][ch][t][w] = acc2;
        g_colpart[3][ch][t][w] = acc3;
    }

    // row partial tail: sum 8 warps x 4 pairpos, store half4
    __syncthreads();
    if (tid < HCH) {
        float s0 = 0.f, s1 = 0.f, s2 = 0.f, s3 = 0.f;
        #pragma unroll
        for (int wp = 0; wp < 8; ++wp) {
            const uint4* rowp = (const uint4*)&s_row[wp][tid][0];
            #pragma unroll
            for (int q = 0; q < 2; ++q) {
                uint4 u = rowp[q];
                float2 a01 = __half22float2(*(const __half2*)&u.x);
                float2 a23 = __half22float2(*(const __half2*)&u.y);
                float2 c01 = __half22float2(*(const __half2*)&u.z);
                float2 c23 = __half22float2(*(const __half2*)&u.w);
                s0 += a01.x + c01.x; s1 += a01.y + c01.y;
                s2 += a23.x + c23.x; s3 += a23.y + c23.y;
            }
        }
        const int h = ch * HCH + tid;
        __half2 o01 = __floats2half2_rn(s0, s1);
        __half2 o23 = __floats2half2_rn(s2, s3);
        g_rowpart[t][wt][h] = make_uint2(*(unsigned*)&o01, *(unsigned*)&o23);
    }
}

// ---------------------------------------------------------------------------
// Reduce: t<90 from column partials; t>=90 from row partials (mirrored).
// ---------------------------------------------------------------------------
__global__ void reduce_kernel(float* __restrict__ out) {
    int idx = blockIdx.x * blockDim.x + threadIdx.x;   // [n][t][w], w fastest
    if (idx >= NB * NT * IW) return;
    const int w  = idx & (IW - 1);
    const int nt = idx >> 9;
    const int t  = nt % NT;
    const int n  = nt / NT;

    float sum = 0.f;
    if (t < NTH) {
        #pragma unroll
        for (int ch = 0; ch < NCH; ++ch)
            sum += g_colpart[n][ch][t][w];
    } else {
        const int th = t - NTH;
        const int h  = IW - 1 - w;
        #pragma unroll
        for (int wt = 0; wt < NWT; ++wt) {
            uint2 u = g_rowpart[th][wt][h];
            if (n < 2) {
                float2 v = __half22float2(*(const __half2*)&u.x);
                sum += (n == 0) ? v.x : v.y;
            } else {
                float2 v = __half22float2(*(const __half2*)&u.y);
                sum += (n == 2) ? v.x : v.y;
            }
        }
    }
    out[n * (IW * NT) + w * NT + t] = sum;
}

// ---------------------------------------------------------------------------
extern "C" void kernel_launch(void* const* d_in, const int* in_sizes, int n_in,
                              void* d_out, int out_size) {
    const float* x  = (const float*)d_in[0];
    const float* th = (const float*)d_in[1];
    if (n_in >= 2 && in_sizes[0] == NT) {
        const float* tmp = x; x = th; th = tmp;
    }
    float* out = (float*)d_out;

    prep_border_kernel<<<(PW * PW + 255) / 256, 256>>>();
    prep_fill_kernel<<<((IW + 1) * (IW + 1) + 255) / 256, 256>>>(x);

    dim3 grid(NTH, NWT, NCH);
    radon_kernel<<<grid, 256>>>(th);

    reduce_kernel<<<(NB * NT * IW + 255) / 256, 256>>>(out);
}

// round 13
// speedup vs baseline: 2.7186x; 1.0148x over previous
#include <cuda_runtime.h>
#include <cuda_fp16.h>

#define IW   512
#define NB   4
#define NT   180
#define NTH  90             // sampled angles; 90..179 via row sums
#define PAD  16
#define PW   (IW + 2*PAD)   // 544
#define NCH  4
#define HCH  (IW / NCH)     // 128
#define NWT  8
#define IMG_STRIDE (IW*IW)
#define OFS  ((float)PAD + 255.5f)     // padded-center offset
#define LO   ((float)PAD - 1.0f)       // nonzero support lower edge
#define HI   ((float)PAD + 512.0f)     // nonzero support upper edge

// 32B entry at (r,c): full 2x2 bilinear stencil x 4 batches, fp16.
struct __align__(32) E32 { uint4 t, b; };

__device__ E32   g_pair [PW * PW];                 // 9.5 MB
__device__ E32   g_pairT[PW * PW];                 // 9.5 MB
__device__ float4 g_colpart[NCH][NTH][IW];         // batches packed per entry
__device__ uint2  g_rowpart[NTH][NWT][IW];         // half4 per (t,wt,h)

// 256-bit global load (sm_100+)
__device__ __forceinline__ void ldg256(const E32* p, uint4& t, uint4& b) {
    asm("ld.global.v8.b32 {%0,%1,%2,%3,%4,%5,%6,%7}, [%8];"
        : "=r"(t.x), "=r"(t.y), "=r"(t.z), "=r"(t.w),
          "=r"(b.x), "=r"(b.y), "=r"(b.z), "=r"(b.w)
        : "l"(p));
}

// ---------------------------------------------------------------------------
__global__ void prep_border_kernel() {
    int idx = blockIdx.x * blockDim.x + threadIdx.x;
    if (idx >= PW * PW) return;
    int row = idx / PW;
    int col = idx - row * PW;
    if ((unsigned)(row - (PAD - 1)) < (unsigned)(IW + 1) &&
        (unsigned)(col - (PAD - 1)) < (unsigned)(IW + 1))
        return;
    const uint4 z = make_uint4(0u, 0u, 0u, 0u);
    g_pair [idx].t = z; g_pair [idx].b = z;
    g_pairT[idx].t = z; g_pairT[idx].b = z;
}

// ---------------------------------------------------------------------------
__global__ void prep_fill_kernel(const float* __restrict__ x) {
    int idx = blockIdx.x * blockDim.x + threadIdx.x;
    if (idx >= (IW + 1) * (IW + 1)) return;
    const int r = idx / (IW + 1) - 1;
    const int c = idx - (r + 1) * (IW + 1) - 1;

    const bool r0 = (unsigned)r < (unsigned)IW;
    const bool r1 = (unsigned)(r + 1) < (unsigned)IW;
    const bool c0 = (unsigned)c < (unsigned)IW;
    const bool c1 = (unsigned)(c + 1) < (unsigned)IW;
    const int base = r * IW + c;

    E32 en, et;
    #pragma unroll
    for (int bb = 0; bb < 4; ++bb) {
        const float* xb = x + bb * IMG_STRIDE;
        float p00 = (r0 && c0) ? xb[base]          : 0.f;
        float p01 = (r0 && c1) ? xb[base + 1]      : 0.f;
        float p10 = (r1 && c0) ? xb[base + IW]     : 0.f;
        float p11 = (r1 && c1) ? xb[base + IW + 1] : 0.f;
        __half2 nt = __floats2half2_rn(p00, p01);
        __half2 nb = __floats2half2_rn(p10, p11);
        __half2 tt = __floats2half2_rn(p00, p10);
        __half2 tb = __floats2half2_rn(p01, p11);
        ((unsigned*)&en.t)[bb] = *(unsigned*)&nt;
        ((unsigned*)&en.b)[bb] = *(unsigned*)&nb;
        ((unsigned*)&et.t)[bb] = *(unsigned*)&tt;
        ((unsigned*)&et.b)[bb] = *(unsigned*)&tb;
    }
    g_pair [(r + PAD) * PW + (c + PAD)] = en;
    g_pairT[(c + PAD) * PW + (r + PAD)] = et;
}

// ---------------------------------------------------------------------------
// Radon for t in 0..89; column sums -> P_t, row sums -> P_{t+90} (mirrored).
// ---------------------------------------------------------------------------
__global__ __launch_bounds__(256, 6) void radon_kernel(const float* __restrict__ theta) {
    __shared__ uint2 s_row[8][HCH][4];   // 32 KB

    const int t    = blockIdx.x;
    const int wt   = blockIdx.y;
    const int ch   = blockIdx.z;
    const int tid  = threadIdx.x;
    const int warp = tid >> 5;
    const int lane = tid & 31;
    const int wl   = lane & 7;
    const int hl   = lane >> 3;
    const int w    = wt * 64 + warp * 8 + wl;

    // zero row-partial slab (skipped k's must read as 0)
    {
        uint4* sr = (uint4*)&s_row[0][0][0];
        #pragma unroll
        for (int i = 0; i < 8; ++i)
            sr[tid + 256 * i] = make_uint4(0u, 0u, 0u, 0u);
    }
    __syncthreads();

    const float rad = theta[t] * 0.017453292519943295f;
    float s, c;
    sincosf(rad, &s, &c);

    float cA, sA, cB, sB;
    const E32* __restrict__ img;
    if (fabsf(s) > fabsf(c)) { cA = -s; sA = c; cB = c;  sB = s; img = g_pairT; }
    else                     { cA = c;  sA = s; cB = -s; sB = c; img = g_pair;  }

    const float wf    = (float)w - 255.5f;
    const float colw  = fmaf(cA, wf, OFS);
    const float roww  = fmaf(cB, wf, OFS);
    const float hbase = (float)(ch * HCH) - 255.5f;

    // warp-uniform valid-k interval (nonzero bilinear support: coord in (LO, HI))
    const float wfa = (float)(wt * 64 + warp * 8) - 255.5f;
    const float wfb = wfa + 7.0f;
    float t1a = cB * wfa, t1b = cB * wfb;
    const float rA = OFS + fminf(t1a, t1b);
    const float rB = OFS + fmaxf(t1a, t1b) + 3.0f * sB;
    const float rh = sB * hbase;
    const float inv4sB = 1.0f / (4.0f * sB);
    float kL = (LO - rB - rh) * inv4sB;
    float kU = (HI - rA - rh) * inv4sB;
    float t2a = cA * wfa, t2b = cA * wfb;
    const float cC = OFS + fminf(t2a, t2b) + fminf(0.f, 3.f * sA);
    const float cD = OFS + fmaxf(t2a, t2b) + fmaxf(0.f, 3.f * sA);
    if (sA > 0.01f) {
        const float inv = 1.0f / (4.0f * sA);
        kL = fmaxf(kL, (LO - cD - sA * hbase) * inv);
        kU = fminf(kU, (HI - cC - sA * hbase) * inv);
    } else if (sA < -0.01f) {
        const float inv = 1.0f / (4.0f * sA);
        kL = fmaxf(kL, (HI - cC - sA * hbase) * inv);
        kU = fminf(kU, (LO - cD - sA * hbase) * inv);
    }
    const int k0 = max(0, (int)floorf(kL));
    const int k1 = min(HCH / 4, (int)floorf(kU) + 1);

    float acc0 = 0.f, acc1 = 0.f, acc2 = 0.f, acc3 = 0.f;
    const unsigned m = 0xFFFFFFFFu;

    if (k0 < k1) {
        float hf = hbase + (float)hl + 4.0f * (float)k0;

        float colv = fmaf(sA, hf, colw);
        float rowv = fmaf(sB, hf, roww);
        float cf = floorf(colv), rf = floorf(rowv);
        uint4 qT, qB;
        ldg256(img + (int)fmaf(rf, (float)PW, cf), qT, qB);
        float fc = colv - cf, fr = rowv - rf;

        for (int k = k0; k < k1; ++k) {
            hf += 4.0f;
            const float colv2 = fmaf(sA, hf, colw);
            const float rowv2 = fmaf(sB, hf, roww);
            const float cf2 = floorf(colv2), rf2 = floorf(rowv2);
            uint4 nT, nB;
            ldg256(img + (int)fmaf(rf2, (float)PW, cf2), nT, nB);

            const float gc = 1.f - fc, gr = 1.f - fr;
            const float w00 = gr * gc, w01 = gr * fc, w10 = fr * gc, w11 = fr * fc;
            const float2 t0 = __half22float2(*(const __half2*)&qT.x);
            const float2 t1 = __half22float2(*(const __half2*)&qT.y);
            const float2 t2 = __half22float2(*(const __half2*)&qT.z);
            const float2 t3 = __half22float2(*(const __half2*)&qT.w);
            const float2 b0 = __half22float2(*(const __half2*)&qB.x);
            const float2 b1 = __half22float2(*(const __half2*)&qB.y);
            const float2 b2 = __half22float2(*(const __half2*)&qB.z);
            const float2 b3 = __half22float2(*(const __half2*)&qB.w);

            float vx = fmaf(t0.x, w00, fmaf(t0.y, w01, fmaf(b0.x, w10, b0.y * w11)));
            float vy = fmaf(t1.x, w00, fmaf(t1.y, w01, fmaf(b1.x, w10, b1.y * w11)));
            float vz = fmaf(t2.x, w00, fmaf(t2.y, w01, fmaf(b2.x, w10, b2.y * w11)));
            float vw = fmaf(t3.x, w00, fmaf(t3.y, w01, fmaf(b3.x, w10, b3.y * w11)));

            acc0 += vx; acc1 += vy; acc2 += vz; acc3 += vw;

            // row partial: fp16 pack + 1-level exchange + pair store
            __half2 h01 = __floats2half2_rn(vx, vy);
            __half2 h23 = __floats2half2_rn(vz, vw);
            unsigned u01 = *(unsigned*)&h01;
            unsigned u23 = *(unsigned*)&h23;
            unsigned r01 = __shfl_xor_sync(m, u01, 1);
            unsigned r23 = __shfl_xor_sync(m, u23, 1);
            __half2 s01 = __hadd2(h01, *(__half2*)&r01);
            __half2 s23 = __hadd2(h23, *(__half2*)&r23);
            if ((wl & 1) == 0)
                s_row[warp][hl + 4 * k][wl >> 1] =
                    make_uint2(*(unsigned*)&s01, *(unsigned*)&s23);

            qT = nT; qB = nB;
            fc = colv2 - cf2;
            fr = rowv2 - rf2;
        }
    }

    // column partial: reduce 4 h-sublanes, one packed STG.128
    acc0 += __shfl_xor_sync(m, acc0, 8);  acc1 += __shfl_xor_sync(m, acc1, 8);
    acc2 += __shfl_xor_sync(m, acc2, 8);  acc3 += __shfl_xor_sync(m, acc3, 8);
    acc0 += __shfl_xor_sync(m, acc0, 16); acc1 += __shfl_xor_sync(m, acc1, 16);
    acc2 += __shfl_xor_sync(m, acc2, 16); acc3 += __shfl_xor_sync(m, acc3, 16);
    if (hl == 0)
        g_colpart[ch][t][w] = make_float4(acc0, acc1, acc2, acc3);

    // row partial tail: sum 8 warps x 4 pairpos, store half4
    __syncthreads();
    if (tid < HCH) {
        float s0 = 0.f, s1 = 0.f, s2 = 0.f, s3 = 0.f;
        #pragma unroll
        for (int wp = 0; wp < 8; ++wp) {
            const uint4* rowp = (const uint4*)&s_row[wp][tid][0];
            #pragma unroll
            for (int q = 0; q < 2; ++q) {
                uint4 u = rowp[q];
                float2 a01 = __half22float2(*(const __half2*)&u.x);
                float2 a23 = __half22float2(*(const __half2*)&u.y);
                float2 c01 = __half22float2(*(const __half2*)&u.z);
                float2 c23 = __half22float2(*(const __half2*)&u.w);
                s0 += a01.x + c01.x; s1 += a01.y + c01.y;
                s2 += a23.x + c23.x; s3 += a23.y + c23.y;
            }
        }
        const int h = ch * HCH + tid;
        __half2 o01 = __floats2half2_rn(s0, s1);
        __half2 o23 = __floats2half2_rn(s2, s3);
        g_rowpart[t][wt][h] = make_uint2(*(unsigned*)&o01, *(unsigned*)&o23);
    }
}

// ---------------------------------------------------------------------------
// Reduce: one thread per (t,w), all 4 batches.
// ---------------------------------------------------------------------------
__global__ void reduce_kernel(float* __restrict__ out) {
    int idx = blockIdx.x * blockDim.x + threadIdx.x;   // t*IW + w
    if (idx >= NT * IW) return;
    const int w = idx & (IW - 1);
    const int t = idx >> 9;

    float s0 = 0.f, s1 = 0.f, s2 = 0.f, s3 = 0.f;
    if (t < NTH) {
        #pragma unroll
        for (int ch = 0; ch < NCH; ++ch) {
            float4 v = g_colpart[ch][t][w];
            s0 += v.x; s1 += v.y; s2 += v.z; s3 += v.w;
        }
    } else {
        const int th = t - NTH;
        const int h  = IW - 1 - w;
        #pragma unroll
        for (int wt = 0; wt < NWT; ++wt) {
            uint2 u = g_rowpart[th][wt][h];
            float2 v01 = __half22float2(*(const __half2*)&u.x);
            float2 v23 = __half22float2(*(const __half2*)&u.y);
            s0 += v01.x; s1 += v01.y; s2 += v23.x; s3 += v23.y;
        }
    }
    const int o = w * NT + t;
    out[o]                  = s0;
    out[o +     IW * NT]    = s1;
    out[o + 2 * IW * NT]    = s2;
    out[o + 3 * IW * NT]    = s3;
}

// ---------------------------------------------------------------------------
extern "C" void kernel_launch(void* const* d_in, const int* in_sizes, int n_in,
                              void* d_out, int out_size) {
    const float* x  = (const float*)d_in[0];
    const float* th = (const float*)d_in[1];
    if (n_in >= 2 && in_sizes[0] == NT) {
        const float* tmp = x; x = th; th = tmp;
    }
    float* out = (float*)d_out;

    prep_border_kernel<<<(PW * PW + 255) / 256, 256>>>();
    prep_fill_kernel<<<((IW + 1) * (IW + 1) + 255) / 256, 256>>>(x);

    dim3 grid(NTH, NWT, NCH);
    radon_kernel<<<grid, 256>>>(th);

    reduce_kernel<<<(NT * IW + 255) / 256, 256>>>(out);
}

// round 14
// speedup vs baseline: 2.7692x; 1.0186x over previous
#include <cuda_runtime.h>
#include <cuda_fp16.h>

#define IW   512
#define NB   4
#define NT   180
#define NTH  90             // sampled angles; 90..179 via row sums
#define PAD  16
#define PW   (IW + 2*PAD)   // 544
#define NCH  4
#define HCH  (IW / NCH)     // 128
#define NWT  8
#define IMG_STRIDE (IW*IW)
#define OFS  ((float)PAD + 255.5f)     // padded-center offset
#define LO   ((float)PAD - 1.0f)       // nonzero support lower edge
#define HI   ((float)PAD + 512.0f)     // nonzero support upper edge

// 32B entry at (r,c): full 2x2 bilinear stencil x 4 batches, fp16.
struct __align__(32) E32 { uint4 t, b; };

__device__ E32   g_pair [PW * PW];                 // 9.5 MB
__device__ E32   g_pairT[PW * PW];                 // 9.5 MB
__device__ float4 g_colpart[NCH][NTH][IW];         // batches packed per entry
__device__ uint2  g_rowpart[NTH][NWT][IW];         // half4 per (t,wt,h)

// 256-bit global load (sm_100+)
__device__ __forceinline__ void ldg256(const E32* p, uint4& t, uint4& b) {
    asm("ld.global.v8.b32 {%0,%1,%2,%3,%4,%5,%6,%7}, [%8];"
        : "=r"(t.x), "=r"(t.y), "=r"(t.z), "=r"(t.w),
          "=r"(b.x), "=r"(b.y), "=r"(b.z), "=r"(b.w)
        : "l"(p));
}

// ---------------------------------------------------------------------------
// Prep: one pass over the padded grid. Interior -> fill, border -> zero.
// ---------------------------------------------------------------------------
__global__ void prep_kernel(const float* __restrict__ x) {
    int idx = blockIdx.x * blockDim.x + threadIdx.x;
    if (idx >= PW * PW) return;
    const int row = idx / PW;
    const int col = idx - row * PW;

    const bool interior =
        (unsigned)(row - (PAD - 1)) < (unsigned)(IW + 1) &&
        (unsigned)(col - (PAD - 1)) < (unsigned)(IW + 1);

    if (!interior) {
        const uint4 z = make_uint4(0u, 0u, 0u, 0u);
        g_pair [idx].t = z; g_pair [idx].b = z;
        g_pairT[idx].t = z; g_pairT[idx].b = z;
        return;
    }

    const int r = row - PAD;                 // -1 .. IW-1  (normal-entry row)
    const int c = col - PAD;                 // -1 .. IW-1

    const bool r0 = (unsigned)r < (unsigned)IW;
    const bool r1 = (unsigned)(r + 1) < (unsigned)IW;
    const bool c0 = (unsigned)c < (unsigned)IW;
    const bool c1 = (unsigned)(c + 1) < (unsigned)IW;
    const int base = r * IW + c;

    E32 en, et;
    #pragma unroll
    for (int bb = 0; bb < 4; ++bb) {
        const float* xb = x + bb * IMG_STRIDE;
        float p00 = (r0 && c0) ? xb[base]          : 0.f;
        float p01 = (r0 && c1) ? xb[base + 1]      : 0.f;
        float p10 = (r1 && c0) ? xb[base + IW]     : 0.f;
        float p11 = (r1 && c1) ? xb[base + IW + 1] : 0.f;
        __half2 nt = __floats2half2_rn(p00, p01);
        __half2 nb = __floats2half2_rn(p10, p11);
        __half2 tt = __floats2half2_rn(p00, p10);
        __half2 tb = __floats2half2_rn(p01, p11);
        ((unsigned*)&en.t)[bb] = *(unsigned*)&nt;
        ((unsigned*)&en.b)[bb] = *(unsigned*)&nb;
        ((unsigned*)&et.t)[bb] = *(unsigned*)&tt;
        ((unsigned*)&et.b)[bb] = *(unsigned*)&tb;
    }
    g_pair [idx] = en;                            // (r+PAD, c+PAD) == idx
    g_pairT[(c + PAD) * PW + (r + PAD)] = et;
}

// ---------------------------------------------------------------------------
// Radon for t in 0..89; column sums -> P_t, row sums -> P_{t+90} (mirrored).
// ---------------------------------------------------------------------------
__global__ __launch_bounds__(256, 6) void radon_kernel(const float* __restrict__ theta) {
    __shared__ uint2 s_row[8][HCH][4];   // 32 KB

    const int t    = blockIdx.x;
    const int wt   = blockIdx.y;
    const int ch   = blockIdx.z;
    const int tid  = threadIdx.x;
    const int warp = tid >> 5;
    const int lane = tid & 31;
    const int wl   = lane & 7;
    const int hl   = lane >> 3;
    const int w    = wt * 64 + warp * 8 + wl;

    // zero row-partial slab (skipped k's must read as 0)
    {
        uint4* sr = (uint4*)&s_row[0][0][0];
        #pragma unroll
        for (int i = 0; i < 8; ++i)
            sr[tid + 256 * i] = make_uint4(0u, 0u, 0u, 0u);
    }
    __syncthreads();

    const float rad = theta[t] * 0.017453292519943295f;
    float s, c;
    sincosf(rad, &s, &c);

    float cA, sA, cB, sB;
    const E32* __restrict__ img;
    if (fabsf(s) > fabsf(c)) { cA = -s; sA = c; cB = c;  sB = s; img = g_pairT; }
    else                     { cA = c;  sA = s; cB = -s; sB = c; img = g_pair;  }

    const float wf    = (float)w - 255.5f;
    const float colw  = fmaf(cA, wf, OFS);
    const float roww  = fmaf(cB, wf, OFS);
    const float hbase = (float)(ch * HCH) - 255.5f;

    // warp-uniform valid-k interval (nonzero bilinear support: coord in (LO, HI))
    const float wfa = (float)(wt * 64 + warp * 8) - 255.5f;
    const float wfb = wfa + 7.0f;
    float t1a = cB * wfa, t1b = cB * wfb;
    const float rA = OFS + fminf(t1a, t1b);
    const float rB = OFS + fmaxf(t1a, t1b) + 3.0f * sB;
    const float rh = sB * hbase;
    const float inv4sB = 1.0f / (4.0f * sB);
    float kL = (LO - rB - rh) * inv4sB;
    float kU = (HI - rA - rh) * inv4sB;
    float t2a = cA * wfa, t2b = cA * wfb;
    const float cC = OFS + fminf(t2a, t2b) + fminf(0.f, 3.f * sA);
    const float cD = OFS + fmaxf(t2a, t2b) + fmaxf(0.f, 3.f * sA);
    if (sA > 0.01f) {
        const float inv = 1.0f / (4.0f * sA);
        kL = fmaxf(kL, (LO - cD - sA * hbase) * inv);
        kU = fminf(kU, (HI - cC - sA * hbase) * inv);
    } else if (sA < -0.01f) {
        const float inv = 1.0f / (4.0f * sA);
        kL = fmaxf(kL, (HI - cC - sA * hbase) * inv);
        kU = fminf(kU, (LO - cD - sA * hbase) * inv);
    }
    const int k0 = max(0, (int)floorf(kL));
    const int k1 = min(HCH / 4, (int)floorf(kU) + 1);

    float acc0 = 0.f, acc1 = 0.f, acc2 = 0.f, acc3 = 0.f;
    const unsigned m = 0xFFFFFFFFu;

    if (k0 < k1) {
        float hf = hbase + (float)hl + 4.0f * (float)k0;

        float colv = fmaf(sA, hf, colw);
        float rowv = fmaf(sB, hf, roww);
        float cf = floorf(colv), rf = floorf(rowv);
        uint4 qT, qB;
        ldg256(img + (int)fmaf(rf, (float)PW, cf), qT, qB);
        float fc = colv - cf, fr = rowv - rf;

        for (int k = k0; k < k1; ++k) {
            hf += 4.0f;
            const float colv2 = fmaf(sA, hf, colw);
            const float rowv2 = fmaf(sB, hf, roww);
            const float cf2 = floorf(colv2), rf2 = floorf(rowv2);
            uint4 nT, nB;
            ldg256(img + (int)fmaf(rf2, (float)PW, cf2), nT, nB);

            const float gc = 1.f - fc, gr = 1.f - fr;
            const float w00 = gr * gc, w01 = gr * fc, w10 = fr * gc, w11 = fr * fc;
            const float2 t0 = __half22float2(*(const __half2*)&qT.x);
            const float2 t1 = __half22float2(*(const __half2*)&qT.y);
            const float2 t2 = __half22float2(*(const __half2*)&qT.z);
            const float2 t3 = __half22float2(*(const __half2*)&qT.w);
            const float2 b0 = __half22float2(*(const __half2*)&qB.x);
            const float2 b1 = __half22float2(*(const __half2*)&qB.y);
            const float2 b2 = __half22float2(*(const __half2*)&qB.z);
            const float2 b3 = __half22float2(*(const __half2*)&qB.w);

            float vx = fmaf(t0.x, w00, fmaf(t0.y, w01, fmaf(b0.x, w10, b0.y * w11)));
            float vy = fmaf(t1.x, w00, fmaf(t1.y, w01, fmaf(b1.x, w10, b1.y * w11)));
            float vz = fmaf(t2.x, w00, fmaf(t2.y, w01, fmaf(b2.x, w10, b2.y * w11)));
            float vw = fmaf(t3.x, w00, fmaf(t3.y, w01, fmaf(b3.x, w10, b3.y * w11)));

            acc0 += vx; acc1 += vy; acc2 += vz; acc3 += vw;

            // row partial: fp16 pack + 1-level exchange + pair store
            __half2 h01 = __floats2half2_rn(vx, vy);
            __half2 h23 = __floats2half2_rn(vz, vw);
            unsigned u01 = *(unsigned*)&h01;
            unsigned u23 = *(unsigned*)&h23;
            unsigned r01 = __shfl_xor_sync(m, u01, 1);
            unsigned r23 = __shfl_xor_sync(m, u23, 1);
            __half2 s01 = __hadd2(h01, *(__half2*)&r01);
            __half2 s23 = __hadd2(h23, *(__half2*)&r23);
            if ((wl & 1) == 0)
                s_row[warp][hl + 4 * k][wl >> 1] =
                    make_uint2(*(unsigned*)&s01, *(unsigned*)&s23);

            qT = nT; qB = nB;
            fc = colv2 - cf2;
            fr = rowv2 - rf2;
        }
    }

    // column partial: reduce 4 h-sublanes, one packed STG.128
    acc0 += __shfl_xor_sync(m, acc0, 8);  acc1 += __shfl_xor_sync(m, acc1, 8);
    acc2 += __shfl_xor_sync(m, acc2, 8);  acc3 += __shfl_xor_sync(m, acc3, 8);
    acc0 += __shfl_xor_sync(m, acc0, 16); acc1 += __shfl_xor_sync(m, acc1, 16);
    acc2 += __shfl_xor_sync(m, acc2, 16); acc3 += __shfl_xor_sync(m, acc3, 16);
    if (hl == 0)
        g_colpart[ch][t][w] = make_float4(acc0, acc1, acc2, acc3);

    // row partial tail: sum 8 warps x 4 pairpos, store half4
    __syncthreads();
    if (tid < HCH) {
        float s0 = 0.f, s1 = 0.f, s2 = 0.f, s3 = 0.f;
        #pragma unroll
        for (int wp = 0; wp < 8; ++wp) {
            const uint4* rowp = (const uint4*)&s_row[wp][tid][0];
            #pragma unroll
            for (int q = 0; q < 2; ++q) {
                uint4 u = rowp[q];
                float2 a01 = __half22float2(*(const __half2*)&u.x);
                float2 a23 = __half22float2(*(const __half2*)&u.y);
                float2 c01 = __half22float2(*(const __half2*)&u.z);
                float2 c23 = __half22float2(*(const __half2*)&u.w);
                s0 += a01.x + c01.x; s1 += a01.y + c01.y;
                s2 += a23.x + c23.x; s3 += a23.y + c23.y;
            }
        }
        const int h = ch * HCH + tid;
        __half2 o01 = __floats2half2_rn(s0, s1);
        __half2 o23 = __floats2half2_rn(s2, s3);
        g_rowpart[t][wt][h] = make_uint2(*(unsigned*)&o01, *(unsigned*)&o23);
    }
}

// ---------------------------------------------------------------------------
// Reduce: two threads per (t,w) (lane pairs via bit 0); each sums half the
// partials, combine with shfl_xor(1). p==0 lane stores all 4 batch outputs.
// ---------------------------------------------------------------------------
__global__ void reduce_kernel(float* __restrict__ out) {
    int idx = blockIdx.x * blockDim.x + threadIdx.x;   // (t*IW + w)*2 + p
    if (idx >= NT * IW * 2) return;
    const int p  = idx & 1;
    const int tw = idx >> 1;
    const int w  = tw & (IW - 1);
    const int t  = tw >> 9;

    float s0 = 0.f, s1 = 0.f, s2 = 0.f, s3 = 0.f;
    if (t < NTH) {
        #pragma unroll
        for (int i = 0; i < NCH / 2; ++i) {
            float4 v = g_colpart[p * (NCH / 2) + i][t][w];
            s0 += v.x; s1 += v.y; s2 += v.z; s3 += v.w;
        }
    } else {
        const int th = t - NTH;
        const int h  = IW - 1 - w;
        #pragma unroll
        for (int i = 0; i < NWT / 2; ++i) {
            uint2 u = g_rowpart[th][p * (NWT / 2) + i][h];
            float2 v01 = __half22float2(*(const __half2*)&u.x);
            float2 v23 = __half22float2(*(const __half2*)&u.y);
            s0 += v01.x; s1 += v01.y; s2 += v23.x; s3 += v23.y;
        }
    }
    const unsigned m = 0xFFFFFFFFu;
    s0 += __shfl_xor_sync(m, s0, 1);
    s1 += __shfl_xor_sync(m, s1, 1);
    s2 += __shfl_xor_sync(m, s2, 1);
    s3 += __shfl_xor_sync(m, s3, 1);

    if (p == 0) {
        const int o = w * NT + t;
        out[o]               = s0;
        out[o +     IW * NT] = s1;
        out[o + 2 * IW * NT] = s2;
        out[o + 3 * IW * NT] = s3;
    }
}

// ---------------------------------------------------------------------------
extern "C" void kernel_launch(void* const* d_in, const int* in_sizes, int n_in,
                              void* d_out, int out_size) {
    const float* x  = (const float*)d_in[0];
    const float* th = (const float*)d_in[1];
    if (n_in >= 2 && in_sizes[0] == NT) {
        const float* tmp = x; x = th; th = tmp;
    }
    float* out = (float*)d_out;

    prep_kernel<<<(PW * PW + 255) / 256, 256>>>(x);

    dim3 grid(NTH, NWT, NCH);
    radon_kernel<<<grid, 256>>>(th);

    reduce_kernel<<<(NT * IW * 2 + 255) / 256, 256>>>(out);
}

// round 15
// speedup vs baseline: 2.7761x; 1.0025x over previous
#include <cuda_runtime.h>
#include <cuda_fp16.h>

#define IW   512
#define NB   4
#define NT   180
#define NTH  90             // sampled angles; 90..179 via row sums
#define PAD  16
#define PW   (IW + 2*PAD)   // 544 = 17*32
#define NCH  4
#define HCH  (IW / NCH)     // 128
#define NWT  8
#define IMG_STRIDE (IW*IW)
#define OFS  ((float)PAD + 255.5f)     // padded-center offset
#define LO   ((float)PAD - 1.0f)       // nonzero support lower edge
#define HI   ((float)PAD + 512.0f)     // nonzero support upper edge

// 32B entry at (r,c): full 2x2 bilinear stencil x 4 batches, fp16.
struct __align__(32) E32 { uint4 t, b; };

__device__ E32   g_pair [PW * PW];                 // 9.5 MB
__device__ E32   g_pairT[PW * PW];                 // 9.5 MB
__device__ float4 g_colpart[NCH][NTH][IW];         // batches packed per entry
__device__ uint2  g_rowpart[NTH][NWT][IW];         // half4 per (t,wt,h)

// 256-bit global load (sm_100+)
__device__ __forceinline__ void ldg256(const E32* p, uint4& t, uint4& b) {
    asm("ld.global.v8.b32 {%0,%1,%2,%3,%4,%5,%6,%7}, [%8];"
        : "=r"(t.x), "=r"(t.y), "=r"(t.z), "=r"(t.w),
          "=r"(b.x), "=r"(b.y), "=r"(b.z), "=r"(b.w)
        : "l"(p));
}

// ---------------------------------------------------------------------------
// Tiled prep: one 32x32-entry tile per block, covering ALL of the padded
// image (borders become zeros via pixel clamp). Pixels staged once in smem;
// both orientations written coalesced.
// ---------------------------------------------------------------------------
__global__ __launch_bounds__(256) void prep_kernel(const float* __restrict__ x) {
    __shared__ float s[4][33 * 33];     // 17.4 KB

    const int Rp0 = blockIdx.y * 32;    // padded-row tile origin
    const int Cp0 = blockIdx.x * 32;    // padded-col tile origin
    const int pr0 = Rp0 - PAD;          // pixel-row of smem row 0
    const int pc0 = Cp0 - PAD;
    const int tid = threadIdx.x;

    // stage 33x33 pixel window x 4 batches (zero-clamped), coalesced reads
    for (int k = tid; k < 33 * 33; k += 256) {
        const int i = k / 33;
        const int j = k - i * 33;
        const int pr = pr0 + i;
        const int pc = pc0 + j;
        const bool v = (unsigned)pr < (unsigned)IW && (unsigned)pc < (unsigned)IW;
        const int off = pr * IW + pc;
        #pragma unroll
        for (int b = 0; b < 4; ++b)
            s[b][k] = v ? x[off + b * IMG_STRIDE] : 0.f;
    }
    __syncthreads();

    // normal-orientation entries: thread -> (i, j), j fastest (coalesced writes)
    #pragma unroll
    for (int q = 0; q < 4; ++q) {
        const int e = tid + q * 256;
        const int i = e >> 5, j = e & 31;
        E32 en;
        #pragma unroll
        for (int b = 0; b < 4; ++b) {
            const float p00 = s[b][i * 33 + j];
            const float p01 = s[b][i * 33 + j + 1];
            const float p10 = s[b][(i + 1) * 33 + j];
            const float p11 = s[b][(i + 1) * 33 + j + 1];
            __half2 nt = __floats2half2_rn(p00, p01);
            __half2 nb = __floats2half2_rn(p10, p11);
            ((unsigned*)&en.t)[b] = *(unsigned*)&nt;
            ((unsigned*)&en.b)[b] = *(unsigned*)&nb;
        }
        g_pair[(Rp0 + i) * PW + (Cp0 + j)] = en;
    }

    // transposed-orientation entries: thread -> (j, i), i fastest
    // (coalesced writes; smem stride-33 reads are bank-conflict-free)
    #pragma unroll
    for (int q = 0; q < 4; ++q) {
        const int e = tid + q * 256;
        const int j = e >> 5, i = e & 31;
        E32 et;
        #pragma unroll
        for (int b = 0; b < 4; ++b) {
            const float p00 = s[b][i * 33 + j];
            const float p01 = s[b][i * 33 + j + 1];
            const float p10 = s[b][(i + 1) * 33 + j];
            const float p11 = s[b][(i + 1) * 33 + j + 1];
            __half2 tt = __floats2half2_rn(p00, p10);
            __half2 tb = __floats2half2_rn(p01, p11);
            ((unsigned*)&et.t)[b] = *(unsigned*)&tt;
            ((unsigned*)&et.b)[b] = *(unsigned*)&tb;
        }
        g_pairT[(Cp0 + j) * PW + (Rp0 + i)] = et;
    }
}

// ---------------------------------------------------------------------------
// Radon for t in 0..89; column sums -> P_t, row sums -> P_{t+90} (mirrored).
// ---------------------------------------------------------------------------
__global__ __launch_bounds__(256, 6) void radon_kernel(const float* __restrict__ theta) {
    __shared__ uint2 s_row[8][HCH][4];   // 32 KB

    const int t    = blockIdx.x;
    const int wt   = blockIdx.y;
    const int ch   = blockIdx.z;
    const int tid  = threadIdx.x;
    const int warp = tid >> 5;
    const int lane = tid & 31;
    const int wl   = lane & 7;
    const int hl   = lane >> 3;
    const int w    = wt * 64 + warp * 8 + wl;

    // zero row-partial slab (skipped k's must read as 0)
    {
        uint4* sr = (uint4*)&s_row[0][0][0];
        #pragma unroll
        for (int i = 0; i < 8; ++i)
            sr[tid + 256 * i] = make_uint4(0u, 0u, 0u, 0u);
    }
    __syncthreads();

    const float rad = theta[t] * 0.017453292519943295f;
    float s, c;
    sincosf(rad, &s, &c);

    float cA, sA, cB, sB;
    const E32* __restrict__ img;
    if (fabsf(s) > fabsf(c)) { cA = -s; sA = c; cB = c;  sB = s; img = g_pairT; }
    else                     { cA = c;  sA = s; cB = -s; sB = c; img = g_pair;  }

    const float wf    = (float)w - 255.5f;
    const float colw  = fmaf(cA, wf, OFS);
    const float roww  = fmaf(cB, wf, OFS);
    const float hbase = (float)(ch * HCH) - 255.5f;

    // warp-uniform valid-k interval (nonzero bilinear support: coord in (LO, HI))
    const float wfa = (float)(wt * 64 + warp * 8) - 255.5f;
    const float wfb = wfa + 7.0f;
    float t1a = cB * wfa, t1b = cB * wfb;
    const float rA = OFS + fminf(t1a, t1b);
    const float rB = OFS + fmaxf(t1a, t1b) + 3.0f * sB;
    const float rh = sB * hbase;
    const float inv4sB = 1.0f / (4.0f * sB);
    float kL = (LO - rB - rh) * inv4sB;
    float kU = (HI - rA - rh) * inv4sB;
    float t2a = cA * wfa, t2b = cA * wfb;
    const float cC = OFS + fminf(t2a, t2b) + fminf(0.f, 3.f * sA);
    const float cD = OFS + fmaxf(t2a, t2b) + fmaxf(0.f, 3.f * sA);
    if (sA > 0.01f) {
        const float inv = 1.0f / (4.0f * sA);
        kL = fmaxf(kL, (LO - cD - sA * hbase) * inv);
        kU = fminf(kU, (HI - cC - sA * hbase) * inv);
    } else if (sA < -0.01f) {
        const float inv = 1.0f / (4.0f * sA);
        kL = fmaxf(kL, (HI - cC - sA * hbase) * inv);
        kU = fminf(kU, (LO - cD - sA * hbase) * inv);
    }
    const int k0 = max(0, (int)floorf(kL));
    const int k1 = min(HCH / 4, (int)floorf(kU) + 1);

    float acc0 = 0.f, acc1 = 0.f, acc2 = 0.f, acc3 = 0.f;
    const unsigned m = 0xFFFFFFFFu;

    if (k0 < k1) {
        float hf = hbase + (float)hl + 4.0f * (float)k0;

        float colv = fmaf(sA, hf, colw);
        float rowv = fmaf(sB, hf, roww);
        float cf = floorf(colv), rf = floorf(rowv);
        uint4 qT, qB;
        ldg256(img + (int)fmaf(rf, (float)PW, cf), qT, qB);
        float fc = colv - cf, fr = rowv - rf;

        for (int k = k0; k < k1; ++k) {
            hf += 4.0f;
            const float colv2 = fmaf(sA, hf, colw);
            const float rowv2 = fmaf(sB, hf, roww);
            const float cf2 = floorf(colv2), rf2 = floorf(rowv2);
            uint4 nT, nB;
            ldg256(img + (int)fmaf(rf2, (float)PW, cf2), nT, nB);

            const float gc = 1.f - fc, gr = 1.f - fr;
            const float w00 = gr * gc, w01 = gr * fc, w10 = fr * gc, w11 = fr * fc;
            const float2 t0 = __half22float2(*(const __half2*)&qT.x);
            const float2 t1 = __half22float2(*(const __half2*)&qT.y);
            const float2 t2 = __half22float2(*(const __half2*)&qT.z);
            const float2 t3 = __half22float2(*(const __half2*)&qT.w);
            const float2 b0 = __half22float2(*(const __half2*)&qB.x);
            const float2 b1 = __half22float2(*(const __half2*)&qB.y);
            const float2 b2 = __half22float2(*(const __half2*)&qB.z);
            const float2 b3 = __half22float2(*(const __half2*)&qB.w);

            float vx = fmaf(t0.x, w00, fmaf(t0.y, w01, fmaf(b0.x, w10, b0.y * w11)));
            float vy = fmaf(t1.x, w00, fmaf(t1.y, w01, fmaf(b1.x, w10, b1.y * w11)));
            float vz = fmaf(t2.x, w00, fmaf(t2.y, w01, fmaf(b2.x, w10, b2.y * w11)));
            float vw = fmaf(t3.x, w00, fmaf(t3.y, w01, fmaf(b3.x, w10, b3.y * w11)));

            acc0 += vx; acc1 += vy; acc2 += vz; acc3 += vw;

            // row partial: fp16 pack + 1-level exchange + pair store
            __half2 h01 = __floats2half2_rn(vx, vy);
            __half2 h23 = __floats2half2_rn(vz, vw);
            unsigned u01 = *(unsigned*)&h01;
            unsigned u23 = *(unsigned*)&h23;
            unsigned r01 = __shfl_xor_sync(m, u01, 1);
            unsigned r23 = __shfl_xor_sync(m, u23, 1);
            __half2 s01 = __hadd2(h01, *(__half2*)&r01);
            __half2 s23 = __hadd2(h23, *(__half2*)&r23);
            if ((wl & 1) == 0)
                s_row[warp][hl + 4 * k][wl >> 1] =
                    make_uint2(*(unsigned*)&s01, *(unsigned*)&s23);

            qT = nT; qB = nB;
            fc = colv2 - cf2;
            fr = rowv2 - rf2;
        }
    }

    // column partial: reduce 4 h-sublanes, one packed STG.128
    acc0 += __shfl_xor_sync(m, acc0, 8);  acc1 += __shfl_xor_sync(m, acc1, 8);
    acc2 += __shfl_xor_sync(m, acc2, 8);  acc3 += __shfl_xor_sync(m, acc3, 8);
    acc0 += __shfl_xor_sync(m, acc0, 16); acc1 += __shfl_xor_sync(m, acc1, 16);
    acc2 += __shfl_xor_sync(m, acc2, 16); acc3 += __shfl_xor_sync(m, acc3, 16);
    if (hl == 0)
        g_colpart[ch][t][w] = make_float4(acc0, acc1, acc2, acc3);

    // row partial tail: sum 8 warps x 4 pairpos, store half4
    __syncthreads();
    if (tid < HCH) {
        float s0 = 0.f, s1 = 0.f, s2 = 0.f, s3 = 0.f;
        #pragma unroll
        for (int wp = 0; wp < 8; ++wp) {
            const uint4* rowp = (const uint4*)&s_row[wp][tid][0];
            #pragma unroll
            for (int q = 0; q < 2; ++q) {
                uint4 u = rowp[q];
                float2 a01 = __half22float2(*(const __half2*)&u.x);
                float2 a23 = __half22float2(*(const __half2*)&u.y);
                float2 c01 = __half22float2(*(const __half2*)&u.z);
                float2 c23 = __half22float2(*(const __half2*)&u.w);
                s0 += a01.x + c01.x; s1 += a01.y + c01.y;
                s2 += a23.x + c23.x; s3 += a23.y + c23.y;
            }
        }
        const int h = ch * HCH + tid;
        __half2 o01 = __floats2half2_rn(s0, s1);
        __half2 o23 = __floats2half2_rn(s2, s3);
        g_rowpart[t][wt][h] = make_uint2(*(unsigned*)&o01, *(unsigned*)&o23);
    }
}

// ---------------------------------------------------------------------------
// Reduce: two threads per (t,w) (lane pairs via bit 0); each sums half the
// partials, combine with shfl_xor(1). p==0 lane stores all 4 batch outputs.
// ---------------------------------------------------------------------------
__global__ void reduce_kernel(float* __restrict__ out) {
    int idx = blockIdx.x * blockDim.x + threadIdx.x;   // (t*IW + w)*2 + p
    if (idx >= NT * IW * 2) return;
    const int p  = idx & 1;
    const int tw = idx >> 1;
    const int w  = tw & (IW - 1);
    const int t  = tw >> 9;

    float s0 = 0.f, s1 = 0.f, s2 = 0.f, s3 = 0.f;
    if (t < NTH) {
        #pragma unroll
        for (int i = 0; i < NCH / 2; ++i) {
            float4 v = g_colpart[p * (NCH / 2) + i][t][w];
            s0 += v.x; s1 += v.y; s2 += v.z; s3 += v.w;
        }
    } else {
        const int th = t - NTH;
        const int h  = IW - 1 - w;
        #pragma unroll
        for (int i = 0; i < NWT / 2; ++i) {
            uint2 u = g_rowpart[th][p * (NWT / 2) + i][h];
            float2 v01 = __half22float2(*(const __half2*)&u.x);
            float2 v23 = __half22float2(*(const __half2*)&u.y);
            s0 += v01.x; s1 += v01.y; s2 += v23.x; s3 += v23.y;
        }
    }
    const unsigned m = 0xFFFFFFFFu;
    s0 += __shfl_xor_sync(m, s0, 1);
    s1 += __shfl_xor_sync(m, s1, 1);
    s2 += __shfl_xor_sync(m, s2, 1);
    s3 += __shfl_xor_sync(m, s3, 1);

    if (p == 0) {
        const int o = w * NT + t;
        out[o]               = s0;
        out[o +     IW * NT] = s1;
        out[o + 2 * IW * NT] = s2;
        out[o + 3 * IW * NT] = s3;
    }
}

// ---------------------------------------------------------------------------
extern "C" void kernel_launch(void* const* d_in, const int* in_sizes, int n_in,
                              void* d_out, int out_size) {
    const float* x  = (const float*)d_in[0];
    const float* th = (const float*)d_in[1];
    if (n_in >= 2 && in_sizes[0] == NT) {
        const float* tmp = x; x = th; th = tmp;
    }
    float* out = (float*)d_out;

    dim3 pgrid(PW / 32, PW / 32);      // 17 x 17
    prep_kernel<<<pgrid, 256>>>(x);

    dim3 grid(NTH, NWT, NCH);
    radon_kernel<<<grid, 256>>>(th);

    reduce_kernel<<<(NT * IW * 2 + 255) / 256, 256>>>(out);
}